// round 1
// baseline (speedup 1.0000x reference)
#include <cuda_runtime.h>
#include <math.h>

#define BB 4
#define NN 2048
#define DD 512
#define HH 8
#define EE 4
#define RR 4
#define TOK (BB*NN)      /* 8192 */
#define HID (RR*DD)      /* 2048 */

// ---------------- scratch (static device memory; no allocations) ----------------
__device__ float g_probs[TOK*EE];
__device__ int   g_assigned[TOK];
__device__ int   g_dtok[TOK];
__device__ float g_rp[TOK];
__device__ float g_h[TOK*DD];          // LN output (reused for both LNs)
__device__ float g_qkv[TOK*3*DD];
__device__ float g_o[TOK*DD];
__device__ float g_z[TOK*DD];
__device__ float g_hid[(size_t)TOK*HID];

// ---------------- router: probs = softmax(x @ r_w + r_b) ----------------
__global__ void router_kernel(const float* __restrict__ x,
                              const float* __restrict__ rw,
                              const float* __restrict__ rb)
{
    int row = blockIdx.x;
    int t = threadIdx.x;                      // 128 threads
    const float* xr = x + (size_t)row * DD;
    float acc0=0.f, acc1=0.f, acc2=0.f, acc3=0.f;
    for (int c = t; c < DD; c += 128) {
        float xv = xr[c];
        acc0 += xv * rw[c*4+0];
        acc1 += xv * rw[c*4+1];
        acc2 += xv * rw[c*4+2];
        acc3 += xv * rw[c*4+3];
    }
    __shared__ float red[4][128];
    red[0][t]=acc0; red[1][t]=acc1; red[2][t]=acc2; red[3][t]=acc3;
    __syncthreads();
    for (int s = 64; s > 0; s >>= 1) {
        if (t < s) {
            red[0][t]+=red[0][t+s]; red[1][t]+=red[1][t+s];
            red[2][t]+=red[2][t+s]; red[3][t]+=red[3][t+s];
        }
        __syncthreads();
    }
    if (t == 0) {
        float l[4]; float mx = -1e30f;
        #pragma unroll
        for (int e=0;e<4;e++){ l[e]=red[e][0]+rb[e]; mx=fmaxf(mx,l[e]); }
        float p[4]; float Z=0.f;
        #pragma unroll
        for (int e=0;e<4;e++){ p[e]=expf(l[e]-mx); Z+=p[e]; }
        float inv=1.f/Z;
        #pragma unroll
        for (int e=0;e<4;e++) g_probs[row*4+e]=p[e]*inv;
    }
}

// ---------------- expert-preferred assignment (exact top-k per expert) ----------------
// One block per batch. Sort (prob desc, index asc) via bitonic sort on 64-bit keys,
// then scan sorted order taking first cap[e] unassigned tokens. e = 3..0.
__global__ void assign_kernel()
{
    __shared__ unsigned long long keys[NN];
    __shared__ int  asg[NN];
    __shared__ int  flg[NN];
    __shared__ int  wsum[32];
    const int caps[4] = {1024, 512, 256, 256};
    int b = blockIdx.x, t = threadIdx.x;      // 1024 threads
    asg[t] = -1; asg[t+1024] = -1;
    __syncthreads();
    for (int e = 3; e >= 0; e--) {
        for (int i = t; i < NN; i += 1024) {
            unsigned pb = __float_as_uint(g_probs[(b*NN+i)*4+e]);  // probs >= 0 -> monotone bits
            keys[i] = ((unsigned long long)(~pb) << 32) | (unsigned)i;
        }
        __syncthreads();
        for (int k = 2; k <= NN; k <<= 1) {
            for (int j = k >> 1; j > 0; j >>= 1) {
                #pragma unroll
                for (int w = 0; w < 2; w++) {
                    int idx = t + w*1024;
                    int l = idx ^ j;
                    if (l > idx) {
                        bool asc = ((idx & k) == 0);
                        unsigned long long a = keys[idx], c2 = keys[l];
                        if ((a > c2) == asc) { keys[idx] = c2; keys[l] = a; }
                    }
                }
                __syncthreads();
            }
        }
        for (int i = t; i < NN; i += 1024) {
            int tok = (int)(keys[i] & 0xFFFFFFFFull);
            flg[i] = (asg[tok] < 0) ? 1 : 0;
        }
        __syncthreads();
        // inclusive prefix sum of flg over 2048 (each thread owns pair 2t,2t+1)
        int v0 = flg[2*t], v1 = flg[2*t+1];
        int s = v0 + v1;
        int lane = t & 31, wid = t >> 5;
        int sc = s;
        #pragma unroll
        for (int o = 1; o < 32; o <<= 1) {
            int u = __shfl_up_sync(0xffffffff, sc, o);
            if (lane >= o) sc += u;
        }
        if (lane == 31) wsum[wid] = sc;
        __syncthreads();
        if (wid == 0) {
            int w = wsum[lane];
            #pragma unroll
            for (int o = 1; o < 32; o <<= 1) {
                int u = __shfl_up_sync(0xffffffff, w, o);
                if (lane >= o) w += u;
            }
            wsum[lane] = w;
        }
        __syncthreads();
        int base = (wid > 0 ? wsum[wid-1] : 0) + (sc - s);
        int cap = caps[e];
        if (flg[2*t] && (base + v0) <= cap) {
            int tok = (int)(keys[2*t] & 0xFFFFFFFFull);
            asg[tok] = e;
        }
        if (flg[2*t+1] && (base + v0 + v1) <= cap) {
            int tok = (int)(keys[2*t+1] & 0xFFFFFFFFull);
            asg[tok] = e;
        }
        __syncthreads();
    }
    int a0 = asg[t];      if (a0 < 0) a0 = 0;
    int a1 = asg[t+1024]; if (a1 < 0) a1 = 0;
    g_assigned[b*NN + t] = a0;
    g_assigned[b*NN + t + 1024] = a1;
}

// ---------------- finalize routing: d_tok, rp, write tail outputs ----------------
__global__ void finalize_kernel(float* __restrict__ out, int out_size)
{
    int i = blockIdx.x*blockDim.x + threadIdx.x;
    if (i >= TOK) return;
    int a = g_assigned[i];
    g_dtok[i] = 64 << a;
    float rp = g_probs[i*4 + a];
    g_rp[i] = rp;
    if (out_size >= TOK*DD + TOK)   out[TOK*DD + i] = (float)a;
    if (out_size >= TOK*DD + 2*TOK) out[TOK*DD + TOK + i] = rp;
}

// ---------------- layernorm * nested feature mask ----------------
__global__ void ln_mask_kernel(const float* __restrict__ x,
                               const float* __restrict__ g,
                               const float* __restrict__ b,
                               float* __restrict__ o)
{
    int row = blockIdx.x;
    int t = threadIdx.x;                      // 256 threads
    const float* xr = x + (size_t)row * DD;
    float v0 = xr[t], v1 = xr[t+256];
    __shared__ float rs[256], rq[256];
    rs[t] = v0 + v1;
    rq[t] = v0*v0 + v1*v1;
    __syncthreads();
    for (int st = 128; st > 0; st >>= 1) {
        if (t < st) { rs[t]+=rs[t+st]; rq[t]+=rq[t+st]; }
        __syncthreads();
    }
    float mu  = rs[0] * (1.f/DD);
    float var = rq[0] * (1.f/DD) - mu*mu;
    float rstd = rsqrtf(var + 1e-5f);
    int d = g_dtok[row];
    float* orow = o + (size_t)row * DD;
    orow[t]     = (t < d)       ? (v0-mu)*rstd*g[t]+b[t]         : 0.f;
    orow[t+256] = (t+256 < d)   ? (v1-mu)*rstd*g[t+256]+b[t+256] : 0.f;
}

// ---------------- fp32 SGEMM 128x128x8, 8x8 microtile, fused epilogues ----------------
__device__ __forceinline__ float gelu_t(float v) {
    float c = v*v*v;
    float t = tanhf(0.7978845608028654f*(v + 0.044715f*c));
    return 0.5f*v*(1.f+t);
}

// EPI 0: qkv mask   1: o-proj -> z = x + mask*(c+b_o)
// EPI 2: ff1 gelu   3: ff2 -> out = z + (alpha*rp+1)*mask*(c+b2f)
template<int EPI>
__global__ void sgemm_kernel(const float* __restrict__ A, const float* __restrict__ B,
                             float* __restrict__ C, int M, int N, int K,
                             const float* __restrict__ bias,
                             const float* __restrict__ add,
                             const float* __restrict__ rp,
                             const float* __restrict__ alpha)
{
    __shared__ float As[8][128];
    __shared__ float Bs[8][128];
    int tid = threadIdx.x;                    // 256
    int bx = blockIdx.x, by = blockIdx.y;
    int tx = tid & 15, ty = tid >> 4;
    int ar = tid >> 1, ac = (tid & 1) * 4;
    int br = tid >> 5, bc = (tid & 31) * 4;
    const float* Ap = A + (size_t)(by*128 + ar)*K + ac;
    const float* Bp = B + (size_t)br*N + bx*128 + bc;
    float acc[8][8];
    #pragma unroll
    for (int i=0;i<8;i++)
        #pragma unroll
        for (int j=0;j<8;j++) acc[i][j]=0.f;

    for (int k0 = 0; k0 < K; k0 += 8) {
        float4 av = *(const float4*)(Ap + k0);
        As[ac+0][ar]=av.x; As[ac+1][ar]=av.y; As[ac+2][ar]=av.z; As[ac+3][ar]=av.w;
        float4 bv = *(const float4*)(Bp + (size_t)k0*N);
        *(float4*)&Bs[br][bc] = bv;
        __syncthreads();
        #pragma unroll
        for (int kk = 0; kk < 8; kk++) {
            float af[8], bf[8];
            *(float4*)&af[0] = *(float4*)&As[kk][ty*8];
            *(float4*)&af[4] = *(float4*)&As[kk][ty*8+4];
            *(float4*)&bf[0] = *(float4*)&Bs[kk][tx*8];
            *(float4*)&bf[4] = *(float4*)&Bs[kk][tx*8+4];
            #pragma unroll
            for (int i=0;i<8;i++)
                #pragma unroll
                for (int j=0;j<8;j++)
                    acc[i][j] += af[i]*bf[j];
        }
        __syncthreads();
    }

    int row0 = by*128 + ty*8, col0 = bx*128 + tx*8;
    float aval = (EPI == 3) ? alpha[0] : 0.f;
    #pragma unroll
    for (int i = 0; i < 8; i++) {
        int r = row0 + i;
        int d = g_dtok[r];
        float gate = (EPI == 3) ? (aval * rp[r] + 1.f) : 0.f;
        #pragma unroll
        for (int j = 0; j < 8; j++) {
            int c = col0 + j;
            float v = acc[i][j];
            size_t oidx = (size_t)r*N + c;
            if (EPI == 0) {
                C[oidx] = ((c & 511) < d) ? v : 0.f;
            } else if (EPI == 1) {
                float t2 = (c < d) ? (v + bias[c]) : 0.f;
                C[oidx] = add[oidx] + t2;
            } else if (EPI == 2) {
                C[oidx] = (c < 4*d) ? gelu_t(v + bias[c]) : 0.f;
            } else {
                float zp = (c < d) ? (v + bias[c]) : 0.f;
                C[oidx] = add[oidx] + gate * zp;
            }
        }
    }
}

// ---------------- flash attention, 64q x 64k tiles, online softmax ----------------
#define ATTN_SMEM ((4*64*68 + 64*17 + 3*64)*4)

__global__ void attn_kernel()
{
    extern __shared__ float sm[];
    float* Qst = sm;                 // [64 dims][68] k-major
    float* Kst = sm + 4352;          // [64 dims][68] k-major
    float* Vs  = sm + 2*4352;        // [64 keys][68] d-major
    float* Ps  = sm + 3*4352;        // [64 rows][68]
    float* rowbuf = sm + 4*4352;     // [64][17]
    float* m_sm = rowbuf + 64*17;
    float* l_sm = m_sm + 64;
    float* sc_sm = l_sm + 64;

    int b = blockIdx.z, h = blockIdx.y, qt = blockIdx.x;
    int t = threadIdx.x;             // 256
    int tx = t & 15, ty = t >> 4;

    const float* qb = g_qkv + ((size_t)(b*NN + qt*64))*1536 + h*64;
    for (int i = t; i < 1024; i += 256) {
        int n = i >> 4, c4 = (i & 15) << 2;
        float4 v = *(const float4*)(qb + (size_t)n*1536 + c4);
        Qst[(c4+0)*68+n]=v.x; Qst[(c4+1)*68+n]=v.y;
        Qst[(c4+2)*68+n]=v.z; Qst[(c4+3)*68+n]=v.w;
    }
    if (t < 64) { m_sm[t] = -1e30f; l_sm[t] = 0.f; }
    float o[4][4];
    #pragma unroll
    for (int i=0;i<4;i++)
        #pragma unroll
        for (int j=0;j<4;j++) o[i][j]=0.f;
    __syncthreads();

    for (int kt = 0; kt < 32; kt++) {
        const float* kb = g_qkv + ((size_t)(b*NN + kt*64))*1536 + 512 + h*64;
        for (int i = t; i < 1024; i += 256) {
            int n = i >> 4, c4 = (i & 15) << 2;
            float4 kv = *(const float4*)(kb + (size_t)n*1536 + c4);
            Kst[(c4+0)*68+n]=kv.x; Kst[(c4+1)*68+n]=kv.y;
            Kst[(c4+2)*68+n]=kv.z; Kst[(c4+3)*68+n]=kv.w;
            float4 vv = *(const float4*)(kb + 512 + (size_t)n*1536 + c4);
            *(float4*)&Vs[n*68 + c4] = vv;
        }
        __syncthreads();

        float s[4][4];
        #pragma unroll
        for (int i=0;i<4;i++)
            #pragma unroll
            for (int j=0;j<4;j++) s[i][j]=0.f;
        #pragma unroll 8
        for (int k = 0; k < 64; k++) {
            float4 qf = *(const float4*)&Qst[k*68 + ty*4];
            float4 kf = *(const float4*)&Kst[k*68 + tx*4];
            s[0][0]+=qf.x*kf.x; s[0][1]+=qf.x*kf.y; s[0][2]+=qf.x*kf.z; s[0][3]+=qf.x*kf.w;
            s[1][0]+=qf.y*kf.x; s[1][1]+=qf.y*kf.y; s[1][2]+=qf.y*kf.z; s[1][3]+=qf.y*kf.w;
            s[2][0]+=qf.z*kf.x; s[2][1]+=qf.z*kf.y; s[2][2]+=qf.z*kf.z; s[2][3]+=qf.z*kf.w;
            s[3][0]+=qf.w*kf.x; s[3][1]+=qf.w*kf.y; s[3][2]+=qf.w*kf.z; s[3][3]+=qf.w*kf.w;
        }
        #pragma unroll
        for (int i=0;i<4;i++)
            #pragma unroll
            for (int j=0;j<4;j++) s[i][j] *= 0.125f;

        #pragma unroll
        for (int r=0;r<4;r++) {
            float pm = fmaxf(fmaxf(s[r][0],s[r][1]), fmaxf(s[r][2],s[r][3]));
            rowbuf[(ty*4+r)*17 + tx] = pm;
        }
        __syncthreads();
        if (t < 64) {
            float mx = rowbuf[t*17];
            #pragma unroll
            for (int j=1;j<16;j++) mx = fmaxf(mx, rowbuf[t*17+j]);
            float mo = m_sm[t];
            float mn = fmaxf(mo, mx);
            sc_sm[t] = __expf(mo - mn);
            m_sm[t] = mn;
        }
        __syncthreads();
        float psum[4] = {0.f,0.f,0.f,0.f};
        #pragma unroll
        for (int r=0;r<4;r++) {
            float mr = m_sm[ty*4+r];
            #pragma unroll
            for (int c=0;c<4;c++) {
                float p = __expf(s[r][c] - mr);
                Ps[(ty*4+r)*68 + tx*4 + c] = p;
                psum[r] += p;
            }
            rowbuf[(ty*4+r)*17 + tx] = psum[r];
        }
        __syncthreads();
        if (t < 64) {
            float su = 0.f;
            #pragma unroll
            for (int j=0;j<16;j++) su += rowbuf[t*17+j];
            l_sm[t] = l_sm[t]*sc_sm[t] + su;
        }
        float scl[4];
        #pragma unroll
        for (int r=0;r<4;r++) scl[r] = sc_sm[ty*4+r];
        #pragma unroll
        for (int r=0;r<4;r++)
            #pragma unroll
            for (int c=0;c<4;c++) o[r][c] *= scl[r];
        #pragma unroll 8
        for (int k = 0; k < 64; k++) {
            float4 vf = *(const float4*)&Vs[k*68 + tx*4];
            float p0 = Ps[(ty*4+0)*68+k];
            float p1 = Ps[(ty*4+1)*68+k];
            float p2 = Ps[(ty*4+2)*68+k];
            float p3 = Ps[(ty*4+3)*68+k];
            o[0][0]+=p0*vf.x; o[0][1]+=p0*vf.y; o[0][2]+=p0*vf.z; o[0][3]+=p0*vf.w;
            o[1][0]+=p1*vf.x; o[1][1]+=p1*vf.y; o[1][2]+=p1*vf.z; o[1][3]+=p1*vf.w;
            o[2][0]+=p2*vf.x; o[2][1]+=p2*vf.y; o[2][2]+=p2*vf.z; o[2][3]+=p2*vf.w;
            o[3][0]+=p3*vf.x; o[3][1]+=p3*vf.y; o[3][2]+=p3*vf.z; o[3][3]+=p3*vf.w;
        }
        __syncthreads();
    }
    #pragma unroll
    for (int r=0;r<4;r++) {
        int gi = b*NN + qt*64 + ty*4 + r;
        bool act = g_dtok[gi] > h*64;
        float inv = act ? (1.f / l_sm[ty*4+r]) : 0.f;
        float* ob = g_o + (size_t)gi*DD + h*64 + tx*4;
        ob[0]=o[r][0]*inv; ob[1]=o[r][1]*inv; ob[2]=o[r][2]*inv; ob[3]=o[r][3]*inv;
    }
}

// ---------------- launcher ----------------
extern "C" void kernel_launch(void* const* d_in, const int* in_sizes, int n_in,
                              void* d_out, int out_size)
{
    const float* x     = (const float*)d_in[0];
    const float* r_w   = (const float*)d_in[1];
    const float* r_b   = (const float*)d_in[2];
    const float* g1    = (const float*)d_in[3];
    const float* b1    = (const float*)d_in[4];
    const float* g2    = (const float*)d_in[5];
    const float* b2    = (const float*)d_in[6];
    const float* w_qkv = (const float*)d_in[7];
    const float* w_o   = (const float*)d_in[8];
    const float* b_o   = (const float*)d_in[9];
    const float* w1    = (const float*)d_in[10];
    const float* b1f   = (const float*)d_in[11];
    const float* w2    = (const float*)d_in[12];
    const float* b2f   = (const float*)d_in[13];
    const float* alpha = (const float*)d_in[14];
    float* out = (float*)d_out;

    float *p_h, *p_qkv, *p_o, *p_z, *p_hid, *p_rp;
    cudaGetSymbolAddress((void**)&p_h,   g_h);
    cudaGetSymbolAddress((void**)&p_qkv, g_qkv);
    cudaGetSymbolAddress((void**)&p_o,   g_o);
    cudaGetSymbolAddress((void**)&p_z,   g_z);
    cudaGetSymbolAddress((void**)&p_hid, g_hid);
    cudaGetSymbolAddress((void**)&p_rp,  g_rp);

    cudaFuncSetAttribute(attn_kernel, cudaFuncAttributeMaxDynamicSharedMemorySize, ATTN_SMEM);

    // 1. routing
    router_kernel<<<TOK, 128>>>(x, r_w, r_b);
    assign_kernel<<<BB, 1024>>>();
    finalize_kernel<<<(TOK+255)/256, 256>>>(out, out_size);

    // 2. attention path
    ln_mask_kernel<<<TOK, 256>>>(x, g1, b1, p_h);
    sgemm_kernel<0><<<dim3(1536/128, TOK/128), 256>>>(p_h, w_qkv, p_qkv, TOK, 1536, 512,
                                                      nullptr, nullptr, nullptr, nullptr);
    attn_kernel<<<dim3(NN/64, HH, BB), 256, ATTN_SMEM>>>();
    sgemm_kernel<1><<<dim3(512/128, TOK/128), 256>>>(p_o, w_o, p_z, TOK, 512, 512,
                                                     b_o, x, nullptr, nullptr);

    // 3. feed-forward path
    ln_mask_kernel<<<TOK, 256>>>(p_z, g2, b2, p_h);
    sgemm_kernel<2><<<dim3(2048/128, TOK/128), 256>>>(p_h, w1, p_hid, TOK, 2048, 512,
                                                      b1f, nullptr, nullptr, nullptr);
    sgemm_kernel<3><<<dim3(512/128, TOK/128), 256>>>(p_hid, w2, out, TOK, 512, 2048,
                                                     b2f, p_z, p_rp, alpha);
}

// round 2
// speedup vs baseline: 2.2657x; 2.2657x over previous
#include <cuda_runtime.h>
#include <math.h>
#include <stdint.h>

#define BB 4
#define NN 2048
#define DD 512
#define HH 8
#define EE 4
#define RR 4
#define TOK (BB*NN)      /* 8192 */
#define HID (RR*DD)      /* 2048 */

// ---------------- scratch (static device memory; no allocations) ----------------
__device__ float g_probs[TOK*EE];
__device__ int   g_assigned[TOK];
__device__ int   g_dtok[TOK];
__device__ float g_rp[TOK];
__device__ float g_h[TOK*DD];
__device__ float g_qkv[TOK*3*DD];
__device__ float g_o[TOK*DD];
__device__ float g_z[TOK*DD];
__device__ float g_hid[(size_t)TOK*HID];

// ---------------- tf32 helpers ----------------
__device__ __forceinline__ float f2tf(float x) {
    uint32_t u;
    asm("cvt.rna.tf32.f32 %0, %1;" : "=r"(u) : "f"(x));
    return __uint_as_float(u);
}

__device__ __forceinline__ void mma_tf32(float* d, const uint32_t* a, uint32_t b0, uint32_t b1) {
    asm volatile("mma.sync.aligned.m16n8k8.row.col.f32.tf32.tf32.f32 "
                 "{%0,%1,%2,%3}, {%4,%5,%6,%7}, {%8,%9}, {%0,%1,%2,%3};\n"
                 : "+f"(d[0]), "+f"(d[1]), "+f"(d[2]), "+f"(d[3])
                 : "r"(a[0]), "r"(a[1]), "r"(a[2]), "r"(a[3]), "r"(b0), "r"(b1));
}

// ---------------- router: probs = softmax(x @ r_w + r_b) (exact fp32) ----------------
__global__ void router_kernel(const float* __restrict__ x,
                              const float* __restrict__ rw,
                              const float* __restrict__ rb)
{
    int row = blockIdx.x;
    int t = threadIdx.x;                      // 128 threads
    const float* xr = x + (size_t)row * DD;
    float acc0=0.f, acc1=0.f, acc2=0.f, acc3=0.f;
    for (int c = t; c < DD; c += 128) {
        float xv = xr[c];
        acc0 += xv * rw[c*4+0];
        acc1 += xv * rw[c*4+1];
        acc2 += xv * rw[c*4+2];
        acc3 += xv * rw[c*4+3];
    }
    __shared__ float red[4][128];
    red[0][t]=acc0; red[1][t]=acc1; red[2][t]=acc2; red[3][t]=acc3;
    __syncthreads();
    for (int s = 64; s > 0; s >>= 1) {
        if (t < s) {
            red[0][t]+=red[0][t+s]; red[1][t]+=red[1][t+s];
            red[2][t]+=red[2][t+s]; red[3][t]+=red[3][t+s];
        }
        __syncthreads();
    }
    if (t == 0) {
        float l[4]; float mx = -1e30f;
        #pragma unroll
        for (int e=0;e<4;e++){ l[e]=red[e][0]+rb[e]; mx=fmaxf(mx,l[e]); }
        float p[4]; float Z=0.f;
        #pragma unroll
        for (int e=0;e<4;e++){ p[e]=expf(l[e]-mx); Z+=p[e]; }
        float inv=1.f/Z;
        #pragma unroll
        for (int e=0;e<4;e++) g_probs[row*4+e]=p[e]*inv;
    }
}

// ---------------- expert-preferred assignment (exact top-k per expert) ----------------
__global__ void assign_kernel()
{
    __shared__ unsigned long long keys[NN];
    __shared__ int  asg[NN];
    __shared__ int  flg[NN];
    __shared__ int  wsum[32];
    const int caps[4] = {1024, 512, 256, 256};
    int b = blockIdx.x, t = threadIdx.x;      // 1024 threads
    asg[t] = -1; asg[t+1024] = -1;
    __syncthreads();
    for (int e = 3; e >= 0; e--) {
        for (int i = t; i < NN; i += 1024) {
            unsigned pb = __float_as_uint(g_probs[(b*NN+i)*4+e]);
            keys[i] = ((unsigned long long)(~pb) << 32) | (unsigned)i;
        }
        __syncthreads();
        for (int k = 2; k <= NN; k <<= 1) {
            for (int j = k >> 1; j > 0; j >>= 1) {
                #pragma unroll
                for (int w = 0; w < 2; w++) {
                    int idx = t + w*1024;
                    int l = idx ^ j;
                    if (l > idx) {
                        bool asc = ((idx & k) == 0);
                        unsigned long long a = keys[idx], c2 = keys[l];
                        if ((a > c2) == asc) { keys[idx] = c2; keys[l] = a; }
                    }
                }
                __syncthreads();
            }
        }
        for (int i = t; i < NN; i += 1024) {
            int tok = (int)(keys[i] & 0xFFFFFFFFull);
            flg[i] = (asg[tok] < 0) ? 1 : 0;
        }
        __syncthreads();
        int v0 = flg[2*t], v1 = flg[2*t+1];
        int s = v0 + v1;
        int lane = t & 31, wid = t >> 5;
        int sc = s;
        #pragma unroll
        for (int o = 1; o < 32; o <<= 1) {
            int u = __shfl_up_sync(0xffffffff, sc, o);
            if (lane >= o) sc += u;
        }
        if (lane == 31) wsum[wid] = sc;
        __syncthreads();
        if (wid == 0) {
            int w = wsum[lane];
            #pragma unroll
            for (int o = 1; o < 32; o <<= 1) {
                int u = __shfl_up_sync(0xffffffff, w, o);
                if (lane >= o) w += u;
            }
            wsum[lane] = w;
        }
        __syncthreads();
        int base = (wid > 0 ? wsum[wid-1] : 0) + (sc - s);
        int cap = caps[e];
        if (flg[2*t] && (base + v0) <= cap) {
            int tok = (int)(keys[2*t] & 0xFFFFFFFFull);
            asg[tok] = e;
        }
        if (flg[2*t+1] && (base + v0 + v1) <= cap) {
            int tok = (int)(keys[2*t+1] & 0xFFFFFFFFull);
            asg[tok] = e;
        }
        __syncthreads();
    }
    int a0 = asg[t];      if (a0 < 0) a0 = 0;
    int a1 = asg[t+1024]; if (a1 < 0) a1 = 0;
    g_assigned[b*NN + t] = a0;
    g_assigned[b*NN + t + 1024] = a1;
}

// ---------------- finalize routing ----------------
__global__ void finalize_kernel(float* __restrict__ out, int out_size)
{
    int i = blockIdx.x*blockDim.x + threadIdx.x;
    if (i >= TOK) return;
    int a = g_assigned[i];
    g_dtok[i] = 64 << a;
    float rp = g_probs[i*4 + a];
    g_rp[i] = rp;
    if (out_size >= TOK*DD + TOK)   out[TOK*DD + i] = (float)a;
    if (out_size >= TOK*DD + 2*TOK) out[TOK*DD + TOK + i] = rp;
}

// ---------------- layernorm * nested feature mask ----------------
__global__ void ln_mask_kernel(const float* __restrict__ x,
                               const float* __restrict__ g,
                               const float* __restrict__ b,
                               float* __restrict__ o)
{
    int row = blockIdx.x;
    int t = threadIdx.x;                      // 256 threads
    const float* xr = x + (size_t)row * DD;
    float v0 = xr[t], v1 = xr[t+256];
    __shared__ float rs[256], rq[256];
    rs[t] = v0 + v1;
    rq[t] = v0*v0 + v1*v1;
    __syncthreads();
    for (int st = 128; st > 0; st >>= 1) {
        if (t < st) { rs[t]+=rs[t+st]; rq[t]+=rq[t+st]; }
        __syncthreads();
    }
    float mu  = rs[0] * (1.f/DD);
    float var = rq[0] * (1.f/DD) - mu*mu;
    float rstd = rsqrtf(var + 1e-5f);
    int d = g_dtok[row];
    float* orow = o + (size_t)row * DD;
    orow[t]     = (t < d)       ? (v0-mu)*rstd*g[t]+b[t]         : 0.f;
    orow[t+256] = (t+256 < d)   ? (v1-mu)*rstd*g[t+256]+b[t+256] : 0.f;
}

// ---------------- tf32 tensor-core GEMM, 128x128x16 tile, fused epilogues ----------------
__device__ __forceinline__ float gelu_t(float v) {
    float c = v*v*v;
    float t = tanhf(0.7978845608028654f*(v + 0.044715f*c));
    return 0.5f*v*(1.f+t);
}

// EPI 0: qkv mask   1: o-proj -> z = x + mask*(c+b_o)
// EPI 2: ff1 gelu   3: ff2 -> out = z + (alpha*rp+1)*mask*(c+b2f)
template<int EPI>
__global__ void tgemm_kernel(const float* __restrict__ A, const float* __restrict__ B,
                             float* __restrict__ C, int M, int N, int K,
                             const float* __restrict__ bias,
                             const float* __restrict__ add,
                             const float* __restrict__ rp,
                             const float* __restrict__ alpha)
{
    __shared__ float As[128][20];   // stride 20 -> frag banks 20q+c all distinct
    __shared__ float Bs[16][136];   // stride 136 -> frag banks 8c+q all distinct

    int tid  = threadIdx.x;         // 256
    int lane = tid & 31;
    int warp = tid >> 5;
    int wm = warp >> 2, wn = warp & 3;   // 2 x 4 warp grid; warp tile 64x32
    int bx = blockIdx.x, by = blockIdx.y;

    float c[4][4][4];
    #pragma unroll
    for (int i=0;i<4;i++)
        #pragma unroll
        for (int j=0;j<4;j++)
            #pragma unroll
            for (int r=0;r<4;r++) c[i][j][r]=0.f;

    // global load slots
    int ar  = tid >> 2;             // 0..63
    int ac  = (tid & 3) << 2;       // 0,4,8,12
    int br  = tid >> 5;             // 0..7
    int bc  = (tid & 31) << 2;      // 0..124
    const float* Aptr  = A + (size_t)(by*128 + ar)*K + ac;
    const float* Aptr2 = Aptr + (size_t)64*K;
    const float* Bptr  = B + (size_t)br*N + bx*128 + bc;
    const float* Bptr2 = Bptr + (size_t)8*N;

    float4 pa0 = *(const float4*)Aptr;
    float4 pa1 = *(const float4*)Aptr2;
    float4 pb0 = *(const float4*)Bptr;
    float4 pb1 = *(const float4*)Bptr2;

    for (int k0 = 0; k0 < K; k0 += 16) {
        // commit prefetched tile to smem (tf32-rounded)
        As[ar][ac+0]=f2tf(pa0.x); As[ar][ac+1]=f2tf(pa0.y); As[ar][ac+2]=f2tf(pa0.z); As[ar][ac+3]=f2tf(pa0.w);
        As[ar+64][ac+0]=f2tf(pa1.x); As[ar+64][ac+1]=f2tf(pa1.y); As[ar+64][ac+2]=f2tf(pa1.z); As[ar+64][ac+3]=f2tf(pa1.w);
        Bs[br][bc+0]=f2tf(pb0.x); Bs[br][bc+1]=f2tf(pb0.y); Bs[br][bc+2]=f2tf(pb0.z); Bs[br][bc+3]=f2tf(pb0.w);
        Bs[br+8][bc+0]=f2tf(pb1.x); Bs[br+8][bc+1]=f2tf(pb1.y); Bs[br+8][bc+2]=f2tf(pb1.z); Bs[br+8][bc+3]=f2tf(pb1.w);
        __syncthreads();

        if (k0 + 16 < K) {
            Aptr += 16; Aptr2 += 16;
            Bptr += (size_t)16*N; Bptr2 += (size_t)16*N;
            pa0 = *(const float4*)Aptr;
            pa1 = *(const float4*)Aptr2;
            pb0 = *(const float4*)Bptr;
            pb1 = *(const float4*)Bptr2;
        }

        #pragma unroll
        for (int kk = 0; kk < 16; kk += 8) {
            uint32_t af[4][4];
            #pragma unroll
            for (int am = 0; am < 4; am++) {
                int r = wm*64 + am*16 + (lane>>2);
                int cc = kk + (lane&3);
                af[am][0] = __float_as_uint(As[r][cc]);
                af[am][1] = __float_as_uint(As[r+8][cc]);
                af[am][2] = __float_as_uint(As[r][cc+4]);
                af[am][3] = __float_as_uint(As[r+8][cc+4]);
            }
            #pragma unroll
            for (int an = 0; an < 4; an++) {
                int cn = wn*32 + an*8 + (lane>>2);
                uint32_t b0 = __float_as_uint(Bs[kk + (lane&3)][cn]);
                uint32_t b1 = __float_as_uint(Bs[kk + 4 + (lane&3)][cn]);
                #pragma unroll
                for (int am = 0; am < 4; am++)
                    mma_tf32(c[am][an], af[am], b0, b1);
            }
        }
        __syncthreads();
    }

    // epilogue
    float aval = (EPI == 3) ? alpha[0] : 0.f;
    #pragma unroll
    for (int am = 0; am < 4; am++) {
        int r0 = by*128 + wm*64 + am*16 + (lane>>2);
        int r1 = r0 + 8;
        int d0 = g_dtok[r0], d1 = g_dtok[r1];
        float gate0 = (EPI == 3) ? (aval * rp[r0] + 1.f) : 0.f;
        float gate1 = (EPI == 3) ? (aval * rp[r1] + 1.f) : 0.f;
        #pragma unroll
        for (int an = 0; an < 4; an++) {
            int col = bx*128 + wn*32 + an*8 + (lane&3)*2;
            #pragma unroll
            for (int h = 0; h < 2; h++) {
                int r = h ? r1 : r0;
                int d = h ? d1 : d0;
                float gate = h ? gate1 : gate0;
                float v0 = c[am][an][2*h], v1 = c[am][an][2*h+1];
                size_t oidx = (size_t)r*N + col;
                float o0, o1;
                if (EPI == 0) {
                    o0 = ((col & 511) < d)     ? v0 : 0.f;
                    o1 = (((col+1) & 511) < d) ? v1 : 0.f;
                } else if (EPI == 1) {
                    o0 = add[oidx]   + ((col   < d) ? (v0 + bias[col])   : 0.f);
                    o1 = add[oidx+1] + ((col+1 < d) ? (v1 + bias[col+1]) : 0.f);
                } else if (EPI == 2) {
                    o0 = (col   < 4*d) ? gelu_t(v0 + bias[col])   : 0.f;
                    o1 = (col+1 < 4*d) ? gelu_t(v1 + bias[col+1]) : 0.f;
                } else {
                    float z0 = (col   < d) ? (v0 + bias[col])   : 0.f;
                    float z1 = (col+1 < d) ? (v1 + bias[col+1]) : 0.f;
                    o0 = add[oidx]   + gate * z0;
                    o1 = add[oidx+1] + gate * z1;
                }
                float2 ov = make_float2(o0, o1);
                *(float2*)(C + oidx) = ov;
            }
        }
    }
}

// ---------------- tensor-core flash attention: 64 q-rows, 4 warps ----------------
// smem: Qs[64][68] | Kst[64][72] (d-major) | Vs[64][72] (k-major)
#define ATTN_SMEM ((64*68 + 64*72 + 64*72)*4)

__global__ void attn_kernel()
{
    extern __shared__ float sm[];
    float* Qs  = sm;                // [64][68]
    float* Kst = sm + 64*68;        // [d][key] stride 72
    float* Vs  = Kst + 64*72;       // [key][d] stride 72

    int b = blockIdx.z, h = blockIdx.y, qt = blockIdx.x;
    int tid = threadIdx.x;          // 128
    int lane = tid & 31;
    int warp = tid >> 5;            // 4 warps, warp owns q-rows warp*16..+15
    int qg = lane >> 2;             // group id 0..7
    int qm = lane & 3;              // member 0..3

    // load Q tile [64 x 64] into Qs
    const float* qb = g_qkv + (size_t)(b*NN + qt*64)*1536 + h*64;
    for (int i = tid; i < 1024; i += 128) {
        int n = i >> 4, c4 = (i & 15) << 2;
        float4 v = *(const float4*)(qb + (size_t)n*1536 + c4);
        float* q = Qs + n*68 + c4;
        q[0]=v.x; q[1]=v.y; q[2]=v.z; q[3]=v.w;
    }
    __syncthreads();

    // hoist Q fragments (8 k-atoms over d=64), tf32-rounded
    uint32_t qf[8][4];
    {
        int r = warp*16 + qg;
        #pragma unroll
        for (int ka = 0; ka < 8; ka++) {
            int cc = ka*8 + qm;
            qf[ka][0] = __float_as_uint(f2tf(Qs[r*68 + cc]));
            qf[ka][1] = __float_as_uint(f2tf(Qs[(r+8)*68 + cc]));
            qf[ka][2] = __float_as_uint(f2tf(Qs[r*68 + cc + 4]));
            qf[ka][3] = __float_as_uint(f2tf(Qs[(r+8)*68 + cc + 4]));
        }
    }

    float o[8][4];
    #pragma unroll
    for (int i=0;i<8;i++)
        #pragma unroll
        for (int j=0;j<4;j++) o[i][j]=0.f;
    float m0 = -1e30f, m1 = -1e30f, l0 = 0.f, l1 = 0.f;

    for (int kt = 0; kt < 32; kt++) {
        __syncthreads();   // previous iteration's reads complete before overwrite
        const float* kb = g_qkv + (size_t)(b*NN + kt*64)*1536 + 512 + h*64;
        for (int i = tid; i < 1024; i += 128) {
            int n = i >> 4, c4 = (i & 15) << 2;
            float4 kv = *(const float4*)(kb + (size_t)n*1536 + c4);
            Kst[(c4+0)*72+n]=f2tf(kv.x); Kst[(c4+1)*72+n]=f2tf(kv.y);
            Kst[(c4+2)*72+n]=f2tf(kv.z); Kst[(c4+3)*72+n]=f2tf(kv.w);
            float4 vv = *(const float4*)(kb + 512 + (size_t)n*1536 + c4);
            float* vp = Vs + n*72 + c4;
            vp[0]=f2tf(vv.x); vp[1]=f2tf(vv.y); vp[2]=f2tf(vv.z); vp[3]=f2tf(vv.w);
        }
        __syncthreads();

        // S = Q @ K^T  (8 n-atoms over 64 keys)
        float s[8][4];
        #pragma unroll
        for (int i=0;i<8;i++)
            #pragma unroll
            for (int j=0;j<4;j++) s[i][j]=0.f;
        #pragma unroll
        for (int ka = 0; ka < 8; ka++) {
            #pragma unroll
            for (int na = 0; na < 8; na++) {
                uint32_t b0 = __float_as_uint(Kst[(ka*8 + qm)*72 + na*8 + qg]);
                uint32_t b1 = __float_as_uint(Kst[(ka*8 + 4 + qm)*72 + na*8 + qg]);
                mma_tf32(s[na], qf[ka], b0, b1);
            }
        }

        // online softmax (rows r0 = warp*16+qg, r1 = +8); quad = lanes sharing qg
        float mx0 = -1e30f, mx1 = -1e30f;
        #pragma unroll
        for (int na = 0; na < 8; na++) {
            s[na][0]*=0.125f; s[na][1]*=0.125f; s[na][2]*=0.125f; s[na][3]*=0.125f;
            mx0 = fmaxf(mx0, fmaxf(s[na][0], s[na][1]));
            mx1 = fmaxf(mx1, fmaxf(s[na][2], s[na][3]));
        }
        mx0 = fmaxf(mx0, __shfl_xor_sync(0xffffffffu, mx0, 1));
        mx0 = fmaxf(mx0, __shfl_xor_sync(0xffffffffu, mx0, 2));
        mx1 = fmaxf(mx1, __shfl_xor_sync(0xffffffffu, mx1, 1));
        mx1 = fmaxf(mx1, __shfl_xor_sync(0xffffffffu, mx1, 2));
        float mn0 = fmaxf(m0, mx0), mn1 = fmaxf(m1, mx1);
        float sc0 = __expf(m0 - mn0), sc1 = __expf(m1 - mn1);
        m0 = mn0; m1 = mn1;

        float sum0 = 0.f, sum1 = 0.f;
        #pragma unroll
        for (int na = 0; na < 8; na++) {
            s[na][0] = __expf(s[na][0] - m0);
            s[na][1] = __expf(s[na][1] - m0);
            s[na][2] = __expf(s[na][2] - m1);
            s[na][3] = __expf(s[na][3] - m1);
            sum0 += s[na][0] + s[na][1];
            sum1 += s[na][2] + s[na][3];
        }
        sum0 += __shfl_xor_sync(0xffffffffu, sum0, 1);
        sum0 += __shfl_xor_sync(0xffffffffu, sum0, 2);
        sum1 += __shfl_xor_sync(0xffffffffu, sum1, 1);
        sum1 += __shfl_xor_sync(0xffffffffu, sum1, 2);
        l0 = l0*sc0 + sum0;
        l1 = l1*sc1 + sum1;

        #pragma unroll
        for (int da = 0; da < 8; da++) {
            o[da][0]*=sc0; o[da][1]*=sc0; o[da][2]*=sc1; o[da][3]*=sc1;
        }

        // P @ V : permute C-fragment -> A-fragment via quad shuffles
        int src0 = (lane & ~3) | (qm >> 1);
        int src1 = src0 + 2;
        bool odd = (qm & 1);
        #pragma unroll
        for (int ka = 0; ka < 8; ka++) {
            float t0 = __shfl_sync(0xffffffffu, s[ka][0], src0);
            float t1 = __shfl_sync(0xffffffffu, s[ka][1], src0);
            float t2 = __shfl_sync(0xffffffffu, s[ka][2], src0);
            float t3 = __shfl_sync(0xffffffffu, s[ka][3], src0);
            float u0 = __shfl_sync(0xffffffffu, s[ka][0], src1);
            float u1 = __shfl_sync(0xffffffffu, s[ka][1], src1);
            float u2 = __shfl_sync(0xffffffffu, s[ka][2], src1);
            float u3 = __shfl_sync(0xffffffffu, s[ka][3], src1);
            uint32_t pa[4];
            pa[0] = __float_as_uint(f2tf(odd ? t1 : t0));
            pa[1] = __float_as_uint(f2tf(odd ? t3 : t2));
            pa[2] = __float_as_uint(f2tf(odd ? u1 : u0));
            pa[3] = __float_as_uint(f2tf(odd ? u3 : u2));
            #pragma unroll
            for (int da = 0; da < 8; da++) {
                uint32_t b0 = __float_as_uint(Vs[(ka*8 + qm)*72 + da*8 + qg]);
                uint32_t b1 = __float_as_uint(Vs[(ka*8 + 4 + qm)*72 + da*8 + qg]);
                mma_tf32(o[da], pa, b0, b1);
            }
        }
    }

    // epilogue: normalize, mask inactive heads, write
    int row0 = qt*64 + warp*16 + qg;
    int tok0 = b*NN + row0, tok1 = tok0 + 8;
    float inv0 = (g_dtok[tok0] > h*64) ? (1.f / l0) : 0.f;
    float inv1 = (g_dtok[tok1] > h*64) ? (1.f / l1) : 0.f;
    #pragma unroll
    for (int da = 0; da < 8; da++) {
        int col = h*64 + da*8 + qm*2;
        float2 v0 = make_float2(o[da][0]*inv0, o[da][1]*inv0);
        float2 v1 = make_float2(o[da][2]*inv1, o[da][3]*inv1);
        *(float2*)(g_o + (size_t)tok0*DD + col) = v0;
        *(float2*)(g_o + (size_t)tok1*DD + col) = v1;
    }
}

// ---------------- launcher ----------------
extern "C" void kernel_launch(void* const* d_in, const int* in_sizes, int n_in,
                              void* d_out, int out_size)
{
    const float* x     = (const float*)d_in[0];
    const float* r_w   = (const float*)d_in[1];
    const float* r_b   = (const float*)d_in[2];
    const float* g1    = (const float*)d_in[3];
    const float* b1    = (const float*)d_in[4];
    const float* g2    = (const float*)d_in[5];
    const float* b2    = (const float*)d_in[6];
    const float* w_qkv = (const float*)d_in[7];
    const float* w_o   = (const float*)d_in[8];
    const float* b_o   = (const float*)d_in[9];
    const float* w1    = (const float*)d_in[10];
    const float* b1f   = (const float*)d_in[11];
    const float* w2    = (const float*)d_in[12];
    const float* b2f   = (const float*)d_in[13];
    const float* alpha = (const float*)d_in[14];
    float* out = (float*)d_out;

    float *p_h, *p_qkv, *p_o, *p_z, *p_hid, *p_rp;
    cudaGetSymbolAddress((void**)&p_h,   g_h);
    cudaGetSymbolAddress((void**)&p_qkv, g_qkv);
    cudaGetSymbolAddress((void**)&p_o,   g_o);
    cudaGetSymbolAddress((void**)&p_z,   g_z);
    cudaGetSymbolAddress((void**)&p_hid, g_hid);
    cudaGetSymbolAddress((void**)&p_rp,  g_rp);

    cudaFuncSetAttribute(attn_kernel, cudaFuncAttributeMaxDynamicSharedMemorySize, ATTN_SMEM);

    // 1. routing
    router_kernel<<<TOK, 128>>>(x, r_w, r_b);
    assign_kernel<<<BB, 1024>>>();
    finalize_kernel<<<(TOK+255)/256, 256>>>(out, out_size);

    // 2. attention path
    ln_mask_kernel<<<TOK, 256>>>(x, g1, b1, p_h);
    tgemm_kernel<0><<<dim3(1536/128, TOK/128), 256>>>(p_h, w_qkv, p_qkv, TOK, 1536, 512,
                                                      nullptr, nullptr, nullptr, nullptr);
    attn_kernel<<<dim3(NN/64, HH, BB), 128, ATTN_SMEM>>>();
    tgemm_kernel<1><<<dim3(512/128, TOK/128), 256>>>(p_o, w_o, p_z, TOK, 512, 512,
                                                     b_o, x, nullptr, nullptr);

    // 3. feed-forward path
    ln_mask_kernel<<<TOK, 256>>>(p_z, g2, b2, p_h);
    tgemm_kernel<2><<<dim3(2048/128, TOK/128), 256>>>(p_h, w1, p_hid, TOK, 2048, 512,
                                                      b1f, nullptr, nullptr, nullptr);
    tgemm_kernel<3><<<dim3(512/128, TOK/128), 256>>>(p_hid, w2, out, TOK, 512, 2048,
                                                     b2f, p_z, p_rp, alpha);
}

// round 4
// speedup vs baseline: 4.9567x; 2.1877x over previous
#include <cuda_runtime.h>
#include <math.h>
#include <stdint.h>

#define BB 4
#define NN 2048
#define DD 512
#define HH 8
#define EE 4
#define RR 4
#define TOK (BB*NN)      /* 8192 */
#define HID (RR*DD)      /* 2048 */

// ---------------- scratch ----------------
__device__ float g_probs[TOK*EE];
__device__ unsigned g_sorted[BB*EE*NN];   // per (b,e): token ids in rank order
__device__ int   g_perm[TOK];             // sorted pos -> orig global token
__device__ float g_rps[TOK];              // router prob of chosen expert, sorted order
__device__ float g_h[TOK*DD];
__device__ float g_qkv[TOK*3*DD];
__device__ float g_o[TOK*DD];
__device__ float g_z[TOK*DD];
__device__ float g_hid[(size_t)TOK*HID];

// d of a sorted position within a batch
__device__ __forceinline__ int d_of_pos(int p) {
    return p < 1024 ? 64 : p < 1536 ? 128 : p < 1792 ? 256 : 512;
}
// d of a 128-row tile (tb = tile index within batch, 0..15)
__device__ __forceinline__ int d_of_tile(int tb) {
    return tb < 8 ? 64 : tb < 12 ? 128 : tb < 14 ? 256 : 512;
}

// ---------------- tf32 helpers ----------------
__device__ __forceinline__ float f2tf(float x) {
    uint32_t u;
    asm("cvt.rna.tf32.f32 %0, %1;" : "=r"(u) : "f"(x));
    return __uint_as_float(u);
}
__device__ __forceinline__ void mma_tf32(float* d, const uint32_t* a, uint32_t b0, uint32_t b1) {
    asm volatile("mma.sync.aligned.m16n8k8.row.col.f32.tf32.tf32.f32 "
                 "{%0,%1,%2,%3}, {%4,%5,%6,%7}, {%8,%9}, {%0,%1,%2,%3};\n"
                 : "+f"(d[0]), "+f"(d[1]), "+f"(d[2]), "+f"(d[3])
                 : "r"(a[0]), "r"(a[1]), "r"(a[2]), "r"(a[3]), "r"(b0), "r"(b1));
}

// ---------------- router (exact fp32) ----------------
__global__ void router_kernel(const float* __restrict__ x,
                              const float* __restrict__ rw,
                              const float* __restrict__ rb)
{
    int row = blockIdx.x;
    int t = threadIdx.x;                      // 128
    const float* xr = x + (size_t)row * DD;
    float acc0=0.f, acc1=0.f, acc2=0.f, acc3=0.f;
    for (int c = t; c < DD; c += 128) {
        float xv = xr[c];
        acc0 += xv * rw[c*4+0];
        acc1 += xv * rw[c*4+1];
        acc2 += xv * rw[c*4+2];
        acc3 += xv * rw[c*4+3];
    }
    __shared__ float red[4][128];
    red[0][t]=acc0; red[1][t]=acc1; red[2][t]=acc2; red[3][t]=acc3;
    __syncthreads();
    for (int s = 64; s > 0; s >>= 1) {
        if (t < s) {
            red[0][t]+=red[0][t+s]; red[1][t]+=red[1][t+s];
            red[2][t]+=red[2][t+s]; red[3][t]+=red[3][t+s];
        }
        __syncthreads();
    }
    if (t == 0) {
        float l[4]; float mx = -1e30f;
        #pragma unroll
        for (int e=0;e<4;e++){ l[e]=red[e][0]+rb[e]; mx=fmaxf(mx,l[e]); }
        float p[4]; float Z=0.f;
        #pragma unroll
        for (int e=0;e<4;e++){ p[e]=expf(l[e]-mx); Z+=p[e]; }
        float inv=1.f/Z;
        #pragma unroll
        for (int e=0;e<4;e++) g_probs[row*4+e]=p[e]*inv;
    }
}

// ---------------- parallel per-(b,e) sort (prob desc, index asc) ----------------
__global__ void sort_kernel()
{
    __shared__ unsigned long long keys[NN];
    int b = blockIdx.x >> 2, e = blockIdx.x & 3;
    int t = threadIdx.x;                      // 1024
    for (int i = t; i < NN; i += 1024) {
        unsigned pb = __float_as_uint(g_probs[(b*NN+i)*4+e]);
        keys[i] = ((unsigned long long)(~pb) << 32) | (unsigned)i;
    }
    __syncthreads();
    for (int k = 2; k <= NN; k <<= 1) {
        for (int j = k >> 1; j > 0; j >>= 1) {
            #pragma unroll
            for (int w = 0; w < 2; w++) {
                int idx = t + w*1024;
                int l = idx ^ j;
                if (l > idx) {
                    bool asc = ((idx & k) == 0);
                    unsigned long long a = keys[idx], c2 = keys[l];
                    if ((a > c2) == asc) { keys[idx] = c2; keys[l] = a; }
                }
            }
            __syncthreads();
        }
    }
    for (int i = t; i < NN; i += 1024)
        g_sorted[(b*4+e)*NN + i] = (unsigned)(keys[i] & 0xFFFFFFFFull);
}

// ---------------- serial claim + deterministic permutation ----------------
__global__ void claim_kernel(float* __restrict__ out, int out_size)
{
    __shared__ int asg[NN];
    __shared__ int wsum[32];
    const int caps[4]  = {1024, 512, 256, 256};
    const int base4[4] = {0, 1024, 1536, 1792};
    int b = blockIdx.x, t = threadIdx.x;      // 1024 threads, pair (2t, 2t+1)
    int lane = t & 31, wid = t >> 5;
    asg[2*t] = -1; asg[2*t+1] = -1;
    __syncthreads();

    // claim, largest expert first
    for (int e = 3; e >= 0; e--) {
        int id0 = (int)g_sorted[(b*4+e)*NN + 2*t];
        int id1 = (int)g_sorted[(b*4+e)*NN + 2*t+1];
        int v0 = (asg[id0] < 0) ? 1 : 0;
        int v1 = (asg[id1] < 0) ? 1 : 0;
        int s = v0 + v1, sc = s;
        #pragma unroll
        for (int o = 1; o < 32; o <<= 1) {
            int u = __shfl_up_sync(0xffffffff, sc, o);
            if (lane >= o) sc += u;
        }
        if (lane == 31) wsum[wid] = sc;
        __syncthreads();
        if (wid == 0) {
            int w = wsum[lane];
            #pragma unroll
            for (int o = 1; o < 32; o <<= 1) {
                int u = __shfl_up_sync(0xffffffff, w, o);
                if (lane >= o) w += u;
            }
            wsum[lane] = w;
        }
        __syncthreads();
        int bs = (wid > 0 ? wsum[wid-1] : 0) + (sc - s);
        if (v0 && (bs + v0) <= caps[e]) asg[id0] = e;
        if (v1 && (bs + v0 + v1) <= caps[e]) asg[id1] = e;
        __syncthreads();
    }

    // deterministic perm by token-index order within each expert
    for (int e = 0; e < 4; e++) {
        int v0 = (asg[2*t] == e) ? 1 : 0;
        int v1 = (asg[2*t+1] == e) ? 1 : 0;
        int s = v0 + v1, sc = s;
        #pragma unroll
        for (int o = 1; o < 32; o <<= 1) {
            int u = __shfl_up_sync(0xffffffff, sc, o);
            if (lane >= o) sc += u;
        }
        if (lane == 31) wsum[wid] = sc;
        __syncthreads();
        if (wid == 0) {
            int w = wsum[lane];
            #pragma unroll
            for (int o = 1; o < 32; o <<= 1) {
                int u = __shfl_up_sync(0xffffffff, w, o);
                if (lane >= o) w += u;
            }
            wsum[lane] = w;
        }
        __syncthreads();
        int bs = (wid > 0 ? wsum[wid-1] : 0) + (sc - s);
        if (v0) {
            int pos = base4[e] + bs;
            g_perm[b*NN + pos] = b*NN + 2*t;
            g_rps[b*NN + pos] = g_probs[(b*NN + 2*t)*4 + e];
        }
        if (v1) {
            int pos = base4[e] + bs + v0;
            g_perm[b*NN + pos] = b*NN + 2*t + 1;
            g_rps[b*NN + pos] = g_probs[(b*NN + 2*t + 1)*4 + e];
        }
        __syncthreads();
    }

    // tail outputs in original order
    #pragma unroll
    for (int w = 0; w < 2; w++) {
        int i = 2*t + w;
        int a = asg[i]; if (a < 0) a = 0;
        int gi = b*NN + i;
        if (out_size >= TOK*DD + TOK)   out[TOK*DD + gi] = (float)a;
        if (out_size >= TOK*DD + 2*TOK) out[TOK*DD + TOK + gi] = g_probs[gi*4 + a];
    }
}

// ---------------- layernorm (optional gather via perm), write only active cols ----------------
template<bool GATHER>
__global__ void ln_mask_kernel(const float* __restrict__ x,
                               const float* __restrict__ g,
                               const float* __restrict__ b,
                               float* __restrict__ o)
{
    int row = blockIdx.x;                     // sorted position
    int t = threadIdx.x;                      // 256
    int src = GATHER ? g_perm[row] : row;
    const float* xr = x + (size_t)src * DD;
    float v0 = xr[t], v1 = xr[t+256];
    __shared__ float rs[256], rq[256];
    rs[t] = v0 + v1;
    rq[t] = v0*v0 + v1*v1;
    __syncthreads();
    for (int st = 128; st > 0; st >>= 1) {
        if (t < st) { rs[t]+=rs[t+st]; rq[t]+=rq[t+st]; }
        __syncthreads();
    }
    float mu  = rs[0] * (1.f/DD);
    float var = rq[0] * (1.f/DD) - mu*mu;
    float rstd = rsqrtf(var + 1e-5f);
    int d = d_of_pos(row & (NN-1));
    float* orow = o + (size_t)row * DD;
    if (t < d)       orow[t]     = (v0-mu)*rstd*g[t]+b[t];
    if (t+256 < d)   orow[t+256] = (v1-mu)*rstd*g[t+256]+b[t+256];
}

// ---------------- tf32 GEMM with nested-dim tile skipping ----------------
__device__ __forceinline__ float gelu_t(float v) {
    float c = v*v*v;
    float t = tanhf(0.7978845608028654f*(v + 0.044715f*c));
    return 0.5f*v*(1.f+t);
}

// EPI 0: qkv (mask, skip empty col tiles)           Keff=d
// EPI 1: o-proj  z = x[perm] + mask*(c+b_o)         Keff=d, copy tiles past d
// EPI 2: ff1 gelu (skip col tiles past 4d)          Keff=d
// EPI 3: ff2  out[perm] = z + gate*mask*(c+b2f)     Keff=4d, copy tiles past d
template<int EPI>
__global__ void tgemm_kernel(const float* __restrict__ A, const float* __restrict__ B,
                             float* __restrict__ C, int M, int N, int K,
                             const float* __restrict__ bias,
                             const float* __restrict__ add,
                             const float* __restrict__ alpha)
{
    int bx = blockIdx.x, by = blockIdx.y;
    int d = d_of_tile(by & 15);
    int col0 = bx * 128;
    int tid  = threadIdx.x;         // 256
    int lane = tid & 31;
    int warp = tid >> 5;

    // tile classification
    if (EPI == 0) { if ((col0 & 511) >= d) return; }
    if (EPI == 2) { if (col0 >= 4*d) return; }
    if (EPI == 1 || EPI == 3) {
        if (col0 >= d) {
            // residual copy tile: 128 rows x 128 cols
            int rr = tid >> 1;
            int cc = (tid & 1) * 64;
            int rg = by*128 + rr;
            int orig = g_perm[rg];
            const float* src = (EPI == 1) ? (add + (size_t)orig*N) : (add + (size_t)rg*N);
            float* dst = (EPI == 1) ? (C + (size_t)rg*N) : (C + (size_t)orig*N);
            #pragma unroll
            for (int j = 0; j < 64; j += 4)
                *(float4*)(dst + col0 + cc + j) = *(const float4*)(src + col0 + cc + j);
            return;
        }
    }
    int Keff = (EPI == 3) ? 4*d : d;

    __shared__ float As[128][20];
    __shared__ float Bs[16][136];

    int wm = warp >> 2, wn = warp & 3;   // 2x4 warps, warp tile 64x32
    float c[4][4][4];
    #pragma unroll
    for (int i=0;i<4;i++)
        #pragma unroll
        for (int j=0;j<4;j++)
            #pragma unroll
            for (int r=0;r<4;r++) c[i][j][r]=0.f;

    int ar  = tid >> 2;
    int ac  = (tid & 3) << 2;
    int br  = tid >> 5;
    int bc  = (tid & 31) << 2;
    const float* Aptr  = A + (size_t)(by*128 + ar)*K + ac;
    const float* Aptr2 = Aptr + (size_t)64*K;
    const float* Bptr  = B + (size_t)br*N + col0 + bc;
    const float* Bptr2 = Bptr + (size_t)8*N;

    float4 pa0 = *(const float4*)Aptr;
    float4 pa1 = *(const float4*)Aptr2;
    float4 pb0 = *(const float4*)Bptr;
    float4 pb1 = *(const float4*)Bptr2;

    for (int k0 = 0; k0 < Keff; k0 += 16) {
        As[ar][ac+0]=f2tf(pa0.x); As[ar][ac+1]=f2tf(pa0.y); As[ar][ac+2]=f2tf(pa0.z); As[ar][ac+3]=f2tf(pa0.w);
        As[ar+64][ac+0]=f2tf(pa1.x); As[ar+64][ac+1]=f2tf(pa1.y); As[ar+64][ac+2]=f2tf(pa1.z); As[ar+64][ac+3]=f2tf(pa1.w);
        Bs[br][bc+0]=f2tf(pb0.x); Bs[br][bc+1]=f2tf(pb0.y); Bs[br][bc+2]=f2tf(pb0.z); Bs[br][bc+3]=f2tf(pb0.w);
        Bs[br+8][bc+0]=f2tf(pb1.x); Bs[br+8][bc+1]=f2tf(pb1.y); Bs[br+8][bc+2]=f2tf(pb1.z); Bs[br+8][bc+3]=f2tf(pb1.w);
        __syncthreads();

        if (k0 + 16 < Keff) {
            Aptr += 16; Aptr2 += 16;
            Bptr += (size_t)16*N; Bptr2 += (size_t)16*N;
            pa0 = *(const float4*)Aptr;
            pa1 = *(const float4*)Aptr2;
            pb0 = *(const float4*)Bptr;
            pb1 = *(const float4*)Bptr2;
        }

        #pragma unroll
        for (int kk = 0; kk < 16; kk += 8) {
            uint32_t af[4][4];
            #pragma unroll
            for (int am = 0; am < 4; am++) {
                int r = wm*64 + am*16 + (lane>>2);
                int cc = kk + (lane&3);
                af[am][0] = __float_as_uint(As[r][cc]);
                af[am][1] = __float_as_uint(As[r+8][cc]);
                af[am][2] = __float_as_uint(As[r][cc+4]);
                af[am][3] = __float_as_uint(As[r+8][cc+4]);
            }
            #pragma unroll
            for (int an = 0; an < 4; an++) {
                int cn = wn*32 + an*8 + (lane>>2);
                uint32_t b0 = __float_as_uint(Bs[kk + (lane&3)][cn]);
                uint32_t b1 = __float_as_uint(Bs[kk + 4 + (lane&3)][cn]);
                #pragma unroll
                for (int am = 0; am < 4; am++)
                    mma_tf32(c[am][an], af[am], b0, b1);
            }
        }
        __syncthreads();
    }

    float aval = (EPI == 3) ? alpha[0] : 0.f;
    #pragma unroll
    for (int am = 0; am < 4; am++) {
        int r0 = by*128 + wm*64 + am*16 + (lane>>2);
        int r1 = r0 + 8;
        float gate0 = (EPI == 3) ? (aval * g_rps[r0] + 1.f) : 0.f;
        float gate1 = (EPI == 3) ? (aval * g_rps[r1] + 1.f) : 0.f;
        int org0 = (EPI == 1 || EPI == 3) ? g_perm[r0] : 0;
        int org1 = (EPI == 1 || EPI == 3) ? g_perm[r1] : 0;
        #pragma unroll
        for (int an = 0; an < 4; an++) {
            int col = col0 + wn*32 + an*8 + (lane&3)*2;
            #pragma unroll
            for (int h2 = 0; h2 < 2; h2++) {
                int r = h2 ? r1 : r0;
                int org = h2 ? org1 : org0;
                float gate = h2 ? gate1 : gate0;
                float v0 = c[am][an][2*h2], v1 = c[am][an][2*h2+1];
                float o0, o1;
                if (EPI == 0) {
                    o0 = ((col & 511) < d)     ? v0 : 0.f;
                    o1 = (((col+1) & 511) < d) ? v1 : 0.f;
                    *(float2*)(C + (size_t)r*N + col) = make_float2(o0, o1);
                } else if (EPI == 1) {
                    size_t xi = (size_t)org*N + col;
                    o0 = add[xi]   + ((col   < d) ? (v0 + bias[col])   : 0.f);
                    o1 = add[xi+1] + ((col+1 < d) ? (v1 + bias[col+1]) : 0.f);
                    *(float2*)(C + (size_t)r*N + col) = make_float2(o0, o1);
                } else if (EPI == 2) {
                    o0 = (col   < 4*d) ? gelu_t(v0 + bias[col])   : 0.f;
                    o1 = (col+1 < 4*d) ? gelu_t(v1 + bias[col+1]) : 0.f;
                    *(float2*)(C + (size_t)r*N + col) = make_float2(o0, o1);
                } else {
                    size_t zi = (size_t)r*N + col;
                    float z0 = (col   < d) ? (v0 + bias[col])   : 0.f;
                    float z1 = (col+1 < d) ? (v1 + bias[col+1]) : 0.f;
                    o0 = add[zi]   + gate * z0;
                    o1 = add[zi+1] + gate * z1;
                    *(float2*)(C + (size_t)org*N + col) = make_float2(o0, o1);
                }
            }
        }
    }
}

// ---------------- tensor-core flash attention on sorted layout ----------------
// per batch: 80 query tiles over active segments; inactive keys folded analytically
#define ATTN_SMEM ((64*68 + 64*72 + 64*72)*4)

__global__ void attn_kernel()
{
    extern __shared__ float sm[];
    float* Qs  = sm;                // [64][68]
    float* Kst = sm + 64*68;        // [d][key] stride 72
    float* Vs  = Kst + 64*72;       // [key][d] stride 72

    int b = blockIdx.y;
    int qi = blockIdx.x;            // 0..79
    int h, qt;
    if (qi < 32)      { h = 0; qt = qi; }
    else if (qi < 48) { h = 1; qt = 16 + (qi - 32); }
    else if (qi < 56) { h = 2; qt = 24 + (qi - 48); }
    else if (qi < 64) { h = 3; qt = 24 + (qi - 56); }
    else              { h = 4 + ((qi - 64) >> 2); qt = 28 + ((qi - 64) & 3); }
    int kt0 = (h == 0) ? 0 : (h == 1) ? 16 : (h < 4) ? 24 : 28;
    int nz = kt0 * 64;              // inactive (zero-score) key count

    int tid = threadIdx.x;          // 128
    int lane = tid & 31;
    int warp = tid >> 5;
    int qg = lane >> 2;
    int qm = lane & 3;

    const float* qb = g_qkv + (size_t)(b*NN + qt*64)*1536 + h*64;
    for (int i = tid; i < 1024; i += 128) {
        int n = i >> 4, c4 = (i & 15) << 2;
        float4 v = *(const float4*)(qb + (size_t)n*1536 + c4);
        float* q = Qs + n*68 + c4;
        q[0]=v.x; q[1]=v.y; q[2]=v.z; q[3]=v.w;
    }
    __syncthreads();

    uint32_t qf[8][4];
    {
        int r = warp*16 + qg;
        #pragma unroll
        for (int ka = 0; ka < 8; ka++) {
            int cc = ka*8 + qm;
            qf[ka][0] = __float_as_uint(f2tf(Qs[r*68 + cc]));
            qf[ka][1] = __float_as_uint(f2tf(Qs[(r+8)*68 + cc]));
            qf[ka][2] = __float_as_uint(f2tf(Qs[r*68 + cc + 4]));
            qf[ka][3] = __float_as_uint(f2tf(Qs[(r+8)*68 + cc + 4]));
        }
    }

    float o[8][4];
    #pragma unroll
    for (int i=0;i<8;i++)
        #pragma unroll
        for (int j=0;j<4;j++) o[i][j]=0.f;
    float m0, m1, l0, l1;
    if (nz > 0) { m0 = 0.f; m1 = 0.f; l0 = (float)nz; l1 = (float)nz; }
    else        { m0 = -1e30f; m1 = -1e30f; l0 = 0.f; l1 = 0.f; }

    for (int kt = kt0; kt < 32; kt++) {
        __syncthreads();
        const float* kb = g_qkv + (size_t)(b*NN + kt*64)*1536 + 512 + h*64;
        for (int i = tid; i < 1024; i += 128) {
            int n = i >> 4, c4 = (i & 15) << 2;
            float4 kv = *(const float4*)(kb + (size_t)n*1536 + c4);
            Kst[(c4+0)*72+n]=f2tf(kv.x); Kst[(c4+1)*72+n]=f2tf(kv.y);
            Kst[(c4+2)*72+n]=f2tf(kv.z); Kst[(c4+3)*72+n]=f2tf(kv.w);
            float4 vv = *(const float4*)(kb + 512 + (size_t)n*1536 + c4);
            float* vp = Vs + n*72 + c4;
            vp[0]=f2tf(vv.x); vp[1]=f2tf(vv.y); vp[2]=f2tf(vv.z); vp[3]=f2tf(vv.w);
        }
        __syncthreads();

        float s[8][4];
        #pragma unroll
        for (int i=0;i<8;i++)
            #pragma unroll
            for (int j=0;j<4;j++) s[i][j]=0.f;
        #pragma unroll
        for (int ka = 0; ka < 8; ka++) {
            #pragma unroll
            for (int na = 0; na < 8; na++) {
                uint32_t b0 = __float_as_uint(Kst[(ka*8 + qm)*72 + na*8 + qg]);
                uint32_t b1 = __float_as_uint(Kst[(ka*8 + 4 + qm)*72 + na*8 + qg]);
                mma_tf32(s[na], qf[ka], b0, b1);
            }
        }

        float mx0 = -1e30f, mx1 = -1e30f;
        #pragma unroll
        for (int na = 0; na < 8; na++) {
            s[na][0]*=0.125f; s[na][1]*=0.125f; s[na][2]*=0.125f; s[na][3]*=0.125f;
            mx0 = fmaxf(mx0, fmaxf(s[na][0], s[na][1]));
            mx1 = fmaxf(mx1, fmaxf(s[na][2], s[na][3]));
        }
        mx0 = fmaxf(mx0, __shfl_xor_sync(0xffffffffu, mx0, 1));
        mx0 = fmaxf(mx0, __shfl_xor_sync(0xffffffffu, mx0, 2));
        mx1 = fmaxf(mx1, __shfl_xor_sync(0xffffffffu, mx1, 1));
        mx1 = fmaxf(mx1, __shfl_xor_sync(0xffffffffu, mx1, 2));
        float mn0 = fmaxf(m0, mx0), mn1 = fmaxf(m1, mx1);
        float sc0 = __expf(m0 - mn0), sc1 = __expf(m1 - mn1);
        m0 = mn0; m1 = mn1;

        float sum0 = 0.f, sum1 = 0.f;
        #pragma unroll
        for (int na = 0; na < 8; na++) {
            s[na][0] = __expf(s[na][0] - m0);
            s[na][1] = __expf(s[na][1] - m0);
            s[na][2] = __expf(s[na][2] - m1);
            s[na][3] = __expf(s[na][3] - m1);
            sum0 += s[na][0] + s[na][1];
            sum1 += s[na][2] + s[na][3];
        }
        sum0 += __shfl_xor_sync(0xffffffffu, sum0, 1);
        sum0 += __shfl_xor_sync(0xffffffffu, sum0, 2);
        sum1 += __shfl_xor_sync(0xffffffffu, sum1, 1);
        sum1 += __shfl_xor_sync(0xffffffffu, sum1, 2);
        l0 = l0*sc0 + sum0;
        l1 = l1*sc1 + sum1;

        #pragma unroll
        for (int da = 0; da < 8; da++) {
            o[da][0]*=sc0; o[da][1]*=sc0; o[da][2]*=sc1; o[da][3]*=sc1;
        }

        int src0 = (lane & ~3) | (qm >> 1);
        int src1 = src0 + 2;
        bool odd = (qm & 1);
        #pragma unroll
        for (int ka = 0; ka < 8; ka++) {
            float t0 = __shfl_sync(0xffffffffu, s[ka][0], src0);
            float t1 = __shfl_sync(0xffffffffu, s[ka][1], src0);
            float t2 = __shfl_sync(0xffffffffu, s[ka][2], src0);
            float t3 = __shfl_sync(0xffffffffu, s[ka][3], src0);
            float u0 = __shfl_sync(0xffffffffu, s[ka][0], src1);
            float u1 = __shfl_sync(0xffffffffu, s[ka][1], src1);
            float u2 = __shfl_sync(0xffffffffu, s[ka][2], src1);
            float u3 = __shfl_sync(0xffffffffu, s[ka][3], src1);
            uint32_t pa[4];
            pa[0] = __float_as_uint(f2tf(odd ? t1 : t0));
            pa[1] = __float_as_uint(f2tf(odd ? t3 : t2));
            pa[2] = __float_as_uint(f2tf(odd ? u1 : u0));
            pa[3] = __float_as_uint(f2tf(odd ? u3 : u2));
            #pragma unroll
            for (int da = 0; da < 8; da++) {
                uint32_t b0 = __float_as_uint(Vs[(ka*8 + qm)*72 + da*8 + qg]);
                uint32_t b1 = __float_as_uint(Vs[(ka*8 + 4 + qm)*72 + da*8 + qg]);
                mma_tf32(o[da], pa, b0, b1);
            }
        }
    }

    int tok0 = b*NN + qt*64 + warp*16 + qg;
    int tok1 = tok0 + 8;
    float inv0 = 1.f / l0;
    float inv1 = 1.f / l1;
    #pragma unroll
    for (int da = 0; da < 8; da++) {
        int col = h*64 + da*8 + qm*2;
        *(float2*)(g_o + (size_t)tok0*DD + col) = make_float2(o[da][0]*inv0, o[da][1]*inv0);
        *(float2*)(g_o + (size_t)tok1*DD + col) = make_float2(o[da][2]*inv1, o[da][3]*inv1);
    }
}

// ---------------- launcher ----------------
extern "C" void kernel_launch(void* const* d_in, const int* in_sizes, int n_in,
                              void* d_out, int out_size)
{
    const float* x     = (const float*)d_in[0];
    const float* r_w   = (const float*)d_in[1];
    const float* r_b   = (const float*)d_in[2];
    const float* g1    = (const float*)d_in[3];
    const float* b1    = (const float*)d_in[4];
    const float* g2    = (const float*)d_in[5];
    const float* b2    = (const float*)d_in[6];
    const float* w_qkv = (const float*)d_in[7];
    const float* w_o   = (const float*)d_in[8];
    const float* b_o   = (const float*)d_in[9];
    const float* w1    = (const float*)d_in[10];
    const float* b1f   = (const float*)d_in[11];
    const float* w2    = (const float*)d_in[12];
    const float* b2f   = (const float*)d_in[13];
    const float* alpha = (const float*)d_in[14];
    float* out = (float*)d_out;

    float *p_h, *p_qkv, *p_o, *p_z, *p_hid;
    cudaGetSymbolAddress((void**)&p_h,   g_h);
    cudaGetSymbolAddress((void**)&p_qkv, g_qkv);
    cudaGetSymbolAddress((void**)&p_o,   g_o);
    cudaGetSymbolAddress((void**)&p_z,   g_z);
    cudaGetSymbolAddress((void**)&p_hid, g_hid);

    cudaFuncSetAttribute(attn_kernel, cudaFuncAttributeMaxDynamicSharedMemorySize, ATTN_SMEM);

    // 1. routing (sorted layout)
    router_kernel<<<TOK, 128>>>(x, r_w, r_b);
    sort_kernel<<<BB*EE, 1024>>>();
    claim_kernel<<<BB, 1024>>>(out, out_size);

    // 2. attention path
    ln_mask_kernel<true><<<TOK, 256>>>(x, g1, b1, p_h);   // gather x via perm
    tgemm_kernel<0><<<dim3(1536/128, TOK/128), 256>>>(p_h, w_qkv, p_qkv, TOK, 1536, 512,
                                                      nullptr, nullptr, nullptr);
    attn_kernel<<<dim3(80, BB), 128, ATTN_SMEM>>>();
    tgemm_kernel<1><<<dim3(512/128, TOK/128), 256>>>(p_o, w_o, p_z, TOK, 512, 512,
                                                     b_o, x, nullptr);

    // 3. feed-forward path
    ln_mask_kernel<false><<<TOK, 256>>>(p_z, g2, b2, p_h); // z already sorted
    tgemm_kernel<2><<<dim3(2048/128, TOK/128), 256>>>(p_h, w1, p_hid, TOK, 2048, 512,
                                                      b1f, nullptr, nullptr);
    tgemm_kernel<3><<<dim3(512/128, TOK/128), 256>>>(p_hid, w2, out, TOK, 512, 2048,
                                                     b2f, p_z, alpha);
}

// round 5
// speedup vs baseline: 8.7228x; 1.7598x over previous
#include <cuda_runtime.h>
#include <cuda_fp16.h>
#include <math.h>
#include <stdint.h>

#define BB 4
#define NN 2048
#define DD 512
#define HH 8
#define EE 4
#define RR 4
#define TOK (BB*NN)      /* 8192 */
#define HID (RR*DD)      /* 2048 */

// ---------------- scratch ----------------
__device__ float g_probs[TOK*EE];
__device__ unsigned g_sorted[BB*EE*NN];
__device__ int    g_perm[TOK];            // sorted pos -> orig global token
__device__ float  g_rps[TOK];
__device__ __half g_h[TOK*DD];            // LN output (LN1: original order, LN2: sorted)
__device__ __half g_qkv[TOK*3*DD];        // sorted order
__device__ __half g_o[TOK*DD];            // sorted order
__device__ float  g_z[TOK*DD];            // sorted order (fp32 residual)
__device__ __half g_hid[(size_t)TOK*HID]; // sorted order

__device__ __forceinline__ int d_of_pos(int p) {
    return p < 1024 ? 64 : p < 1536 ? 128 : p < 1792 ? 256 : 512;
}
__device__ __forceinline__ int d_of_tile(int tb) {
    return tb < 8 ? 64 : tb < 12 ? 128 : tb < 14 ? 256 : 512;
}

// ---------------- mma / ldmatrix helpers ----------------
__device__ __forceinline__ void mma_f16(float* d, const uint32_t* a, uint32_t b0, uint32_t b1) {
    asm volatile("mma.sync.aligned.m16n8k16.row.col.f32.f16.f16.f32 "
                 "{%0,%1,%2,%3}, {%4,%5,%6,%7}, {%8,%9}, {%0,%1,%2,%3};\n"
                 : "+f"(d[0]), "+f"(d[1]), "+f"(d[2]), "+f"(d[3])
                 : "r"(a[0]), "r"(a[1]), "r"(a[2]), "r"(a[3]), "r"(b0), "r"(b1));
}
__device__ __forceinline__ void ldsm_x4(uint32_t& r0, uint32_t& r1, uint32_t& r2, uint32_t& r3, uint32_t addr) {
    asm volatile("ldmatrix.sync.aligned.m8n8.x4.shared.b16 {%0,%1,%2,%3}, [%4];"
                 : "=r"(r0), "=r"(r1), "=r"(r2), "=r"(r3) : "r"(addr));
}
__device__ __forceinline__ void ldsm_x2t(uint32_t& r0, uint32_t& r1, uint32_t addr) {
    asm volatile("ldmatrix.sync.aligned.m8n8.x2.trans.shared.b16 {%0,%1}, [%2];"
                 : "=r"(r0), "=r"(r1) : "r"(addr));
}
__device__ __forceinline__ uint32_t packh2(float a, float b) {
    __half2 h = __floats2half2_rn(a, b);
    return *(uint32_t*)&h;
}

// ---------------- router (exact fp32) ----------------
__global__ void router_kernel(const float* __restrict__ x,
                              const float* __restrict__ rw,
                              const float* __restrict__ rb)
{
    int row = blockIdx.x;
    int t = threadIdx.x;                      // 128
    const float* xr = x + (size_t)row * DD;
    float acc0=0.f, acc1=0.f, acc2=0.f, acc3=0.f;
    for (int c = t; c < DD; c += 128) {
        float xv = xr[c];
        acc0 += xv * rw[c*4+0];
        acc1 += xv * rw[c*4+1];
        acc2 += xv * rw[c*4+2];
        acc3 += xv * rw[c*4+3];
    }
    __shared__ float red[4][128];
    red[0][t]=acc0; red[1][t]=acc1; red[2][t]=acc2; red[3][t]=acc3;
    __syncthreads();
    for (int s = 64; s > 0; s >>= 1) {
        if (t < s) {
            red[0][t]+=red[0][t+s]; red[1][t]+=red[1][t+s];
            red[2][t]+=red[2][t+s]; red[3][t]+=red[3][t+s];
        }
        __syncthreads();
    }
    if (t == 0) {
        float l[4]; float mx = -1e30f;
        #pragma unroll
        for (int e=0;e<4;e++){ l[e]=red[e][0]+rb[e]; mx=fmaxf(mx,l[e]); }
        float p[4]; float Z=0.f;
        #pragma unroll
        for (int e=0;e<4;e++){ p[e]=expf(l[e]-mx); Z+=p[e]; }
        float inv=1.f/Z;
        #pragma unroll
        for (int e=0;e<4;e++) g_probs[row*4+e]=p[e]*inv;
    }
}

// ---------------- parallel per-(b,e) sort (prob desc, index asc) ----------------
__global__ void sort_kernel()
{
    __shared__ unsigned long long keys[NN];
    int b = blockIdx.x >> 2, e = blockIdx.x & 3;
    int t = threadIdx.x;                      // 1024
    for (int i = t; i < NN; i += 1024) {
        unsigned pb = __float_as_uint(g_probs[(b*NN+i)*4+e]);
        keys[i] = ((unsigned long long)(~pb) << 32) | (unsigned)i;
    }
    __syncthreads();
    for (int k = 2; k <= NN; k <<= 1) {
        for (int j = k >> 1; j > 0; j >>= 1) {
            #pragma unroll
            for (int w = 0; w < 2; w++) {
                int idx = t + w*1024;
                int l = idx ^ j;
                if (l > idx) {
                    bool asc = ((idx & k) == 0);
                    unsigned long long a = keys[idx], c2 = keys[l];
                    if ((a > c2) == asc) { keys[idx] = c2; keys[l] = a; }
                }
            }
            __syncthreads();
        }
    }
    for (int i = t; i < NN; i += 1024)
        g_sorted[(b*4+e)*NN + i] = (unsigned)(keys[i] & 0xFFFFFFFFull);
}

// ---------------- serial claim + deterministic permutation ----------------
__global__ void claim_kernel(float* __restrict__ out, int out_size)
{
    __shared__ int asg[NN];
    __shared__ int wsum[32];
    const int caps[4]  = {1024, 512, 256, 256};
    const int base4[4] = {0, 1024, 1536, 1792};
    int b = blockIdx.x, t = threadIdx.x;      // 1024 threads
    int lane = t & 31, wid = t >> 5;
    asg[2*t] = -1; asg[2*t+1] = -1;
    __syncthreads();

    for (int e = 3; e >= 0; e--) {
        int id0 = (int)g_sorted[(b*4+e)*NN + 2*t];
        int id1 = (int)g_sorted[(b*4+e)*NN + 2*t+1];
        int v0 = (asg[id0] < 0) ? 1 : 0;
        int v1 = (asg[id1] < 0) ? 1 : 0;
        int s = v0 + v1, sc = s;
        #pragma unroll
        for (int o = 1; o < 32; o <<= 1) {
            int u = __shfl_up_sync(0xffffffff, sc, o);
            if (lane >= o) sc += u;
        }
        if (lane == 31) wsum[wid] = sc;
        __syncthreads();
        if (wid == 0) {
            int w = wsum[lane];
            #pragma unroll
            for (int o = 1; o < 32; o <<= 1) {
                int u = __shfl_up_sync(0xffffffff, w, o);
                if (lane >= o) w += u;
            }
            wsum[lane] = w;
        }
        __syncthreads();
        int bs = (wid > 0 ? wsum[wid-1] : 0) + (sc - s);
        if (v0 && (bs + v0) <= caps[e]) asg[id0] = e;
        if (v1 && (bs + v0 + v1) <= caps[e]) asg[id1] = e;
        __syncthreads();
    }

    for (int e = 0; e < 4; e++) {
        int v0 = (asg[2*t] == e) ? 1 : 0;
        int v1 = (asg[2*t+1] == e) ? 1 : 0;
        int s = v0 + v1, sc = s;
        #pragma unroll
        for (int o = 1; o < 32; o <<= 1) {
            int u = __shfl_up_sync(0xffffffff, sc, o);
            if (lane >= o) sc += u;
        }
        if (lane == 31) wsum[wid] = sc;
        __syncthreads();
        if (wid == 0) {
            int w = wsum[lane];
            #pragma unroll
            for (int o = 1; o < 32; o <<= 1) {
                int u = __shfl_up_sync(0xffffffff, w, o);
                if (lane >= o) w += u;
            }
            wsum[lane] = w;
        }
        __syncthreads();
        int bs = (wid > 0 ? wsum[wid-1] : 0) + (sc - s);
        if (v0) {
            int pos = base4[e] + bs;
            g_perm[b*NN + pos] = b*NN + 2*t;
            g_rps[b*NN + pos] = g_probs[(b*NN + 2*t)*4 + e];
        }
        if (v1) {
            int pos = base4[e] + bs + v0;
            g_perm[b*NN + pos] = b*NN + 2*t + 1;
            g_rps[b*NN + pos] = g_probs[(b*NN + 2*t + 1)*4 + e];
        }
        __syncthreads();
    }

    #pragma unroll
    for (int w = 0; w < 2; w++) {
        int i = 2*t + w;
        int a = asg[i]; if (a < 0) a = 0;
        int gi = b*NN + i;
        if (out_size >= TOK*DD + TOK)   out[TOK*DD + gi] = (float)a;
        if (out_size >= TOK*DD + 2*TOK) out[TOK*DD + TOK + gi] = g_probs[gi*4 + a];
    }
}

// ---------------- layernorm: warp per row, no mask/perm, writes fp16 ----------------
__global__ void ln_kernel(const float* __restrict__ x,
                          const float* __restrict__ g,
                          const float* __restrict__ b,
                          __half* __restrict__ o)
{
    int lane = threadIdx.x & 31, warp = threadIdx.x >> 5;
    int row = blockIdx.x * 8 + warp;
    const float* xr = x + (size_t)row * DD;
    float4 v[4];
    float s = 0.f, q = 0.f;
    #pragma unroll
    for (int i = 0; i < 4; i++) {
        v[i] = *(const float4*)(xr + (i*32 + lane)*4);
        s += v[i].x + v[i].y + v[i].z + v[i].w;
        q += v[i].x*v[i].x + v[i].y*v[i].y + v[i].z*v[i].z + v[i].w*v[i].w;
    }
    #pragma unroll
    for (int off = 16; off > 0; off >>= 1) {
        s += __shfl_xor_sync(0xffffffffu, s, off);
        q += __shfl_xor_sync(0xffffffffu, q, off);
    }
    float mu = s * (1.f/DD);
    float var = q * (1.f/DD) - mu*mu;
    float rstd = rsqrtf(var + 1e-5f);
    __half* orow = o + (size_t)row * DD;
    #pragma unroll
    for (int i = 0; i < 4; i++) {
        int idx = (i*32 + lane)*4;
        float4 gv = *(const float4*)(g + idx);
        float4 bv = *(const float4*)(b + idx);
        float o0 = (v[i].x - mu)*rstd*gv.x + bv.x;
        float o1 = (v[i].y - mu)*rstd*gv.y + bv.y;
        float o2 = (v[i].z - mu)*rstd*gv.z + bv.z;
        float o3 = (v[i].w - mu)*rstd*gv.w + bv.w;
        uint2 pk = make_uint2(packh2(o0, o1), packh2(o2, o3));
        *(uint2*)(orow + idx) = pk;
    }
}

// ---------------- fp16 GEMM, 128x128 tile, K-chunk 32, fused epilogues ----------------
__device__ __forceinline__ float gelu_t(float v) {
    float c = v*v*v;
    float t = tanhf(0.7978845608028654f*(v + 0.044715f*c));
    return 0.5f*v*(1.f+t);
}

// EPI 0: qkv (A row-gather via perm; output mask; skip empty col tiles)   Keff=d
// EPI 1: o-proj  z = x[perm] + mask*(c+b_o)                                Keff=d
// EPI 2: ff1 gelu (skip col tiles past 4d)                                 Keff=d
// EPI 3: ff2  out[perm] = z + gate*mask*(c+b2f)                            Keff=4d
template<int EPI>
__global__ void tgemm_kernel(const __half* __restrict__ A, const float* __restrict__ B,
                             void* __restrict__ Cv, int N, int K,
                             const float* __restrict__ bias,
                             const float* __restrict__ add,
                             const float* __restrict__ alpha)
{
    int bx = blockIdx.x, by = blockIdx.y;
    int d = d_of_tile(by & 15);
    int col0 = bx * 128;
    int tid  = threadIdx.x;         // 256
    int lane = tid & 31;
    int warp = tid >> 5;

    if (EPI == 0) { if ((col0 & 511) >= d) return; }
    if (EPI == 2) { if (col0 >= 4*d) return; }
    if (EPI == 1 || EPI == 3) {
        if (col0 >= d) {
            // residual copy tile (fp32)
            int rr = tid >> 1;
            int cc = (tid & 1) * 64;
            int rg = by*128 + rr;
            int orig = g_perm[rg];
            const float* src = (EPI == 1) ? (add + (size_t)orig*N) : (add + (size_t)rg*N);
            float* dst = (EPI == 1) ? ((float*)Cv + (size_t)rg*N) : ((float*)Cv + (size_t)orig*N);
            #pragma unroll
            for (int j = 0; j < 64; j += 4)
                *(float4*)(dst + col0 + cc + j) = *(const float4*)(src + col0 + cc + j);
            return;
        }
    }
    int Keff = (EPI == 3) ? 4*d : d;

    __shared__ __half As[128][40];    // stride 40 halves = 20 words: conflict-free ldsm rows
    __shared__ __half Bs[32][136];    // stride 136 halves = 68 words: ldsm rows 4k banks

    int wm = warp >> 2, wn = warp & 3;   // 2x4 warps, warp tile 64x32
    float c[4][4][4];
    #pragma unroll
    for (int i=0;i<4;i++)
        #pragma unroll
        for (int j=0;j<4;j++)
            #pragma unroll
            for (int r=0;r<4;r++) c[i][j][r]=0.f;

    // global slots
    int ar  = tid >> 1;                // 0..127
    int ach = (tid & 1) * 16;          // half offset 0/16
    int rowA0 = by*128 + ar;
    int rowA = (EPI == 0) ? g_perm[rowA0] : rowA0;
    const __half* Ag = A + (size_t)rowA*K + ach;
    int bk  = tid >> 3;                // 0..31
    int bn0 = (tid & 7) * 16;          // 0..112
    const float* Bg = B + (size_t)bk*N + col0 + bn0;

    uint4 pa0 = *(const uint4*)(Ag);
    uint4 pa1 = *(const uint4*)(Ag + 8);
    float4 pb[4];
    #pragma unroll
    for (int i=0;i<4;i++) pb[i] = *(const float4*)(Bg + 4*i);

    uint32_t asb = (uint32_t)__cvta_generic_to_shared(&As[0][0]);
    uint32_t bsb = (uint32_t)__cvta_generic_to_shared(&Bs[0][0]);

    for (int k0 = 0; k0 < Keff; k0 += 32) {
        *(uint4*)(&As[ar][ach])     = pa0;
        *(uint4*)(&As[ar][ach + 8]) = pa1;
        #pragma unroll
        for (int i=0;i<4;i++) {
            uint2 pk = make_uint2(packh2(pb[i].x, pb[i].y), packh2(pb[i].z, pb[i].w));
            *(uint2*)(&Bs[bk][bn0 + 4*i]) = pk;
        }
        __syncthreads();

        if (k0 + 32 < Keff) {
            Ag += 32;
            Bg += (size_t)32*N;
            pa0 = *(const uint4*)(Ag);
            pa1 = *(const uint4*)(Ag + 8);
            #pragma unroll
            for (int i=0;i<4;i++) pb[i] = *(const float4*)(Bg + 4*i);
        }

        #pragma unroll
        for (int kk = 0; kk < 32; kk += 16) {
            uint32_t af[4][4];
            #pragma unroll
            for (int am = 0; am < 4; am++) {
                int m = lane >> 3;
                int row = wm*64 + am*16 + (lane & 7) + (m & 1)*8;
                int col = kk + (m >> 1)*8;
                ldsm_x4(af[am][0], af[am][1], af[am][2], af[am][3],
                        asb + row*80 + col*2);
            }
            #pragma unroll
            for (int an = 0; an < 4; an++) {
                int brow = kk + (lane & 15);
                int bcol = wn*32 + an*8;
                uint32_t b0, b1;
                ldsm_x2t(b0, b1, bsb + brow*272 + bcol*2);
                #pragma unroll
                for (int am = 0; am < 4; am++)
                    mma_f16(c[am][an], af[am], b0, b1);
            }
        }
        __syncthreads();
    }

    float aval = (EPI == 3) ? alpha[0] : 0.f;
    #pragma unroll
    for (int am = 0; am < 4; am++) {
        int r0 = by*128 + wm*64 + am*16 + (lane>>2);
        int r1 = r0 + 8;
        float gate0 = (EPI == 3) ? (aval * g_rps[r0] + 1.f) : 0.f;
        float gate1 = (EPI == 3) ? (aval * g_rps[r1] + 1.f) : 0.f;
        int org0 = (EPI == 1 || EPI == 3) ? g_perm[r0] : 0;
        int org1 = (EPI == 1 || EPI == 3) ? g_perm[r1] : 0;
        #pragma unroll
        for (int an = 0; an < 4; an++) {
            int col = col0 + wn*32 + an*8 + (lane&3)*2;
            #pragma unroll
            for (int h2 = 0; h2 < 2; h2++) {
                int r = h2 ? r1 : r0;
                int org = h2 ? org1 : org0;
                float gate = h2 ? gate1 : gate0;
                float v0 = c[am][an][2*h2], v1 = c[am][an][2*h2+1];
                if (EPI == 0) {
                    float o0 = ((col & 511) < d)     ? v0 : 0.f;
                    float o1 = (((col+1) & 511) < d) ? v1 : 0.f;
                    *(uint32_t*)((__half*)Cv + (size_t)r*N + col) = packh2(o0, o1);
                } else if (EPI == 1) {
                    size_t xi = (size_t)org*N + col;
                    float o0 = add[xi]   + ((col   < d) ? (v0 + bias[col])   : 0.f);
                    float o1 = add[xi+1] + ((col+1 < d) ? (v1 + bias[col+1]) : 0.f);
                    *(float2*)((float*)Cv + (size_t)r*N + col) = make_float2(o0, o1);
                } else if (EPI == 2) {
                    float o0 = gelu_t(v0 + bias[col]);
                    float o1 = gelu_t(v1 + bias[col+1]);
                    *(uint32_t*)((__half*)Cv + (size_t)r*N + col) = packh2(o0, o1);
                } else {
                    size_t zi = (size_t)r*N + col;
                    float z0 = (col   < d) ? (v0 + bias[col])   : 0.f;
                    float z1 = (col+1 < d) ? (v1 + bias[col+1]) : 0.f;
                    float o0 = add[zi]   + gate * z0;
                    float o1 = add[zi+1] + gate * z1;
                    *(float2*)((float*)Cv + (size_t)org*N + col) = make_float2(o0, o1);
                }
            }
        }
    }
}

// ---------------- fp16 flash attention on sorted layout ----------------
__global__ void attn_kernel()
{
    __shared__ __half Qs[64][72];
    __shared__ __half Ks[64][72];   // [key][dim]
    __shared__ __half Vs[64][72];   // [key][dim]

    int b = blockIdx.y;
    int qi = blockIdx.x;            // 0..79
    int h, qt;
    if (qi < 32)      { h = 0; qt = qi; }
    else if (qi < 48) { h = 1; qt = 16 + (qi - 32); }
    else if (qi < 56) { h = 2; qt = 24 + (qi - 48); }
    else if (qi < 64) { h = 3; qt = 24 + (qi - 56); }
    else              { h = 4 + ((qi - 64) >> 2); qt = 28 + ((qi - 64) & 3); }
    int kt0 = (h == 0) ? 0 : (h == 1) ? 16 : (h < 4) ? 24 : 28;
    int nz = kt0 * 64;

    int tid = threadIdx.x;          // 128
    int lane = tid & 31;
    int warp = tid >> 5;

    uint32_t vsb = (uint32_t)__cvta_generic_to_shared(&Vs[0][0]);

    // load Q tile [64 tokens x 64 dims] (half copy)
    const __half* qb = g_qkv + (size_t)(b*NN + qt*64)*1536 + h*64;
    for (int i = tid; i < 512; i += 128) {
        int n = i >> 3, c8 = (i & 7) * 8;
        *(uint4*)(&Qs[n][c8]) = *(const uint4*)(qb + (size_t)n*1536 + c8);
    }
    __syncthreads();

    // hoist Q fragments: 4 k-atoms of 16 over d=64
    uint32_t qf[4][4];
    {
        int r = warp*16 + (lane >> 2);
        #pragma unroll
        for (int ka = 0; ka < 4; ka++) {
            int cc = ka*16 + (lane & 3)*2;
            qf[ka][0] = *(const uint32_t*)(&Qs[r][cc]);
            qf[ka][1] = *(const uint32_t*)(&Qs[r+8][cc]);
            qf[ka][2] = *(const uint32_t*)(&Qs[r][cc+8]);
            qf[ka][3] = *(const uint32_t*)(&Qs[r+8][cc+8]);
        }
    }

    float o[8][4];
    #pragma unroll
    for (int i=0;i<8;i++)
        #pragma unroll
        for (int j=0;j<4;j++) o[i][j]=0.f;
    float m0, m1, l0, l1;
    if (nz > 0) { m0 = 0.f; m1 = 0.f; l0 = (float)nz; l1 = (float)nz; }
    else        { m0 = -1e30f; m1 = -1e30f; l0 = 0.f; l1 = 0.f; }

    for (int kt = kt0; kt < 32; kt++) {
        __syncthreads();
        const __half* kb = g_qkv + (size_t)(b*NN + kt*64)*1536 + 512 + h*64;
        for (int i = tid; i < 512; i += 128) {
            int n = i >> 3, c8 = (i & 7) * 8;
            *(uint4*)(&Ks[n][c8]) = *(const uint4*)(kb + (size_t)n*1536 + c8);
            *(uint4*)(&Vs[n][c8]) = *(const uint4*)(kb + 512 + (size_t)n*1536 + c8);
        }
        __syncthreads();

        // S = Q @ K^T : B-frag from Ks[n][k] (pairs contiguous in dim)
        float s[8][4];
        #pragma unroll
        for (int i=0;i<8;i++)
            #pragma unroll
            for (int j=0;j<4;j++) s[i][j]=0.f;
        #pragma unroll
        for (int ka = 0; ka < 4; ka++) {
            #pragma unroll
            for (int na = 0; na < 8; na++) {
                int n = na*8 + (lane >> 2);
                int k = ka*16 + (lane & 3)*2;
                uint32_t b0 = *(const uint32_t*)(&Ks[n][k]);
                uint32_t b1 = *(const uint32_t*)(&Ks[n][k+8]);
                mma_f16(s[na], qf[ka], b0, b1);
            }
        }

        // online softmax
        float mx0 = -1e30f, mx1 = -1e30f;
        #pragma unroll
        for (int na = 0; na < 8; na++) {
            s[na][0]*=0.125f; s[na][1]*=0.125f; s[na][2]*=0.125f; s[na][3]*=0.125f;
            mx0 = fmaxf(mx0, fmaxf(s[na][0], s[na][1]));
            mx1 = fmaxf(mx1, fmaxf(s[na][2], s[na][3]));
        }
        mx0 = fmaxf(mx0, __shfl_xor_sync(0xffffffffu, mx0, 1));
        mx0 = fmaxf(mx0, __shfl_xor_sync(0xffffffffu, mx0, 2));
        mx1 = fmaxf(mx1, __shfl_xor_sync(0xffffffffu, mx1, 1));
        mx1 = fmaxf(mx1, __shfl_xor_sync(0xffffffffu, mx1, 2));
        float mn0 = fmaxf(m0, mx0), mn1 = fmaxf(m1, mx1);
        float sc0 = __expf(m0 - mn0), sc1 = __expf(m1 - mn1);
        m0 = mn0; m1 = mn1;

        float sum0 = 0.f, sum1 = 0.f;
        #pragma unroll
        for (int na = 0; na < 8; na++) {
            s[na][0] = __expf(s[na][0] - m0);
            s[na][1] = __expf(s[na][1] - m0);
            s[na][2] = __expf(s[na][2] - m1);
            s[na][3] = __expf(s[na][3] - m1);
            sum0 += s[na][0] + s[na][1];
            sum1 += s[na][2] + s[na][3];
        }
        sum0 += __shfl_xor_sync(0xffffffffu, sum0, 1);
        sum0 += __shfl_xor_sync(0xffffffffu, sum0, 2);
        sum1 += __shfl_xor_sync(0xffffffffu, sum1, 1);
        sum1 += __shfl_xor_sync(0xffffffffu, sum1, 2);
        l0 = l0*sc0 + sum0;
        l1 = l1*sc1 + sum1;

        #pragma unroll
        for (int da = 0; da < 8; da++) {
            o[da][0]*=sc0; o[da][1]*=sc0; o[da][2]*=sc1; o[da][3]*=sc1;
        }

        // P @ V : A-frags are packed S C-frags (no shuffles); V B-frags via ldmatrix.trans
        #pragma unroll
        for (int ka = 0; ka < 4; ka++) {
            uint32_t pa[4];
            pa[0] = packh2(s[2*ka][0],   s[2*ka][1]);
            pa[1] = packh2(s[2*ka][2],   s[2*ka][3]);
            pa[2] = packh2(s[2*ka+1][0], s[2*ka+1][1]);
            pa[3] = packh2(s[2*ka+1][2], s[2*ka+1][3]);
            uint32_t rowaddr = vsb + (ka*16 + (lane & 15))*144;
            #pragma unroll
            for (int da = 0; da < 8; da++) {
                uint32_t b0, b1;
                ldsm_x2t(b0, b1, rowaddr + da*16);
                mma_f16(o[da], pa, b0, b1);
            }
        }
    }

    int tok0 = b*NN + qt*64 + warp*16 + (lane>>2);
    int tok1 = tok0 + 8;
    float inv0 = 1.f / l0;
    float inv1 = 1.f / l1;
    #pragma unroll
    for (int da = 0; da < 8; da++) {
        int col = h*64 + da*8 + (lane&3)*2;
        *(uint32_t*)(g_o + (size_t)tok0*DD + col) = packh2(o[da][0]*inv0, o[da][1]*inv0);
        *(uint32_t*)(g_o + (size_t)tok1*DD + col) = packh2(o[da][2]*inv1, o[da][3]*inv1);
    }
}

// ---------------- launcher ----------------
extern "C" void kernel_launch(void* const* d_in, const int* in_sizes, int n_in,
                              void* d_out, int out_size)
{
    const float* x     = (const float*)d_in[0];
    const float* r_w   = (const float*)d_in[1];
    const float* r_b   = (const float*)d_in[2];
    const float* g1    = (const float*)d_in[3];
    const float* b1    = (const float*)d_in[4];
    const float* g2    = (const float*)d_in[5];
    const float* b2    = (const float*)d_in[6];
    const float* w_qkv = (const float*)d_in[7];
    const float* w_o   = (const float*)d_in[8];
    const float* b_o   = (const float*)d_in[9];
    const float* w1    = (const float*)d_in[10];
    const float* b1f   = (const float*)d_in[11];
    const float* w2    = (const float*)d_in[12];
    const float* b2f   = (const float*)d_in[13];
    const float* alpha = (const float*)d_in[14];
    float* out = (float*)d_out;

    __half *p_h, *p_qkv, *p_o, *p_hid;
    float *p_z;
    cudaGetSymbolAddress((void**)&p_h,   g_h);
    cudaGetSymbolAddress((void**)&p_qkv, g_qkv);
    cudaGetSymbolAddress((void**)&p_o,   g_o);
    cudaGetSymbolAddress((void**)&p_z,   g_z);
    cudaGetSymbolAddress((void**)&p_hid, g_hid);

    // 1. routing (sorted layout)
    router_kernel<<<TOK, 128>>>(x, r_w, r_b);
    sort_kernel<<<BB*EE, 1024>>>();
    claim_kernel<<<BB, 1024>>>(out, out_size);

    // 2. attention path
    ln_kernel<<<TOK/8, 256>>>(x, g1, b1, p_h);            // original order, unmasked
    tgemm_kernel<0><<<dim3(1536/128, TOK/128), 256>>>(p_h, w_qkv, p_qkv, 1536, 512,
                                                      nullptr, nullptr, nullptr);
    attn_kernel<<<dim3(80, BB), 128>>>();
    tgemm_kernel<1><<<dim3(512/128, TOK/128), 256>>>(p_o, w_o, p_z, 512, 512,
                                                     b_o, x, nullptr);

    // 3. feed-forward path
    ln_kernel<<<TOK/8, 256>>>(p_z, g2, b2, p_h);          // sorted order, unmasked
    tgemm_kernel<2><<<dim3(2048/128, TOK/128), 256>>>(p_h, w1, p_hid, 2048, 512,
                                                      b1f, nullptr, nullptr);
    tgemm_kernel<3><<<dim3(512/128, TOK/128), 256>>>(p_hid, w2, out, 512, 2048,
                                                     b2f, p_z, alpha);
}

// round 7
// speedup vs baseline: 10.6041x; 1.2157x over previous
#include <cuda_runtime.h>
#include <cuda_fp16.h>
#include <math.h>
#include <stdint.h>

#define BB 4
#define NN 2048
#define DD 512
#define HH 8
#define EE 4
#define RR 4
#define TOK (BB*NN)      /* 8192 */
#define HID (RR*DD)      /* 2048 */

// weight fp16 cache offsets (halves)
#define W_QKV_OFF 0
#define W_O_OFF   786432
#define W1_OFF    1048576
#define W2_OFF    2097152
#define W_TOTAL   3145728

// ---------------- scratch ----------------
__device__ float g_probs[TOK*EE];
__device__ unsigned g_sorted[BB*EE*NN];
__device__ int    g_perm[TOK];
__device__ float  g_rps[TOK];
__device__ __align__(16) __half g_wh[W_TOTAL];
__device__ __align__(16) __half g_h[TOK*DD];
__device__ __align__(16) __half g_qkv[TOK*3*DD];
__device__ __align__(16) __half g_o[TOK*DD];
__device__ __align__(16) float  g_z[TOK*DD];
__device__ __align__(16) __half g_hid[(size_t)TOK*HID];

__device__ __forceinline__ int d_of_tile(int tb) {
    return tb < 8 ? 64 : tb < 12 ? 128 : tb < 14 ? 256 : 512;
}

// ---------------- helpers ----------------
__device__ __forceinline__ void mma_f16(float* d, const uint32_t* a, uint32_t b0, uint32_t b1) {
    asm volatile("mma.sync.aligned.m16n8k16.row.col.f32.f16.f16.f32 "
                 "{%0,%1,%2,%3}, {%4,%5,%6,%7}, {%8,%9}, {%0,%1,%2,%3};\n"
                 : "+f"(d[0]), "+f"(d[1]), "+f"(d[2]), "+f"(d[3])
                 : "r"(a[0]), "r"(a[1]), "r"(a[2]), "r"(a[3]), "r"(b0), "r"(b1));
}
__device__ __forceinline__ void ldsm_x4(uint32_t& r0, uint32_t& r1, uint32_t& r2, uint32_t& r3, uint32_t addr) {
    asm volatile("ldmatrix.sync.aligned.m8n8.x4.shared.b16 {%0,%1,%2,%3}, [%4];"
                 : "=r"(r0), "=r"(r1), "=r"(r2), "=r"(r3) : "r"(addr));
}
__device__ __forceinline__ void ldsm_x2t(uint32_t& r0, uint32_t& r1, uint32_t addr) {
    asm volatile("ldmatrix.sync.aligned.m8n8.x2.trans.shared.b16 {%0,%1}, [%2];"
                 : "=r"(r0), "=r"(r1) : "r"(addr));
}
__device__ __forceinline__ uint32_t packh2(float a, float b) {
    __half2 h = __floats2half2_rn(a, b);
    return *(uint32_t*)&h;
}
__device__ __forceinline__ void cp_async16(uint32_t saddr, const void* gaddr) {
    asm volatile("cp.async.ca.shared.global [%0], [%1], 16;\n" :: "r"(saddr), "l"(gaddr));
}
__device__ __forceinline__ void cp_commit() {
    asm volatile("cp.async.commit_group;\n" ::: "memory");
}
__device__ __forceinline__ void cp_wait0() {
    asm volatile("cp.async.wait_group 0;\n" ::: "memory");
}

// ---------------- weight conversion fp32 -> fp16 ----------------
__global__ void wconv_kernel(const float* __restrict__ wqkv, const float* __restrict__ wo,
                             const float* __restrict__ w1,   const float* __restrict__ w2)
{
    size_t off = ((size_t)blockIdx.x*256 + threadIdx.x) * 4;
    if (off >= W_TOTAL) return;
    const float* src;
    if (off < W_O_OFF)      src = wqkv + off;
    else if (off < W1_OFF)  src = wo + (off - W_O_OFF);
    else if (off < W2_OFF)  src = w1 + (off - W1_OFF);
    else                    src = w2 + (off - W2_OFF);
    float4 v = *(const float4*)src;
    *(uint2*)(g_wh + off) = make_uint2(packh2(v.x, v.y), packh2(v.z, v.w));
}

// ---------------- fused layernorm (+ optional router), warp per row ----------------
template<bool ROUTER>
__global__ void ln_router_kernel(const float* __restrict__ x,
                                 const float* __restrict__ g,
                                 const float* __restrict__ b,
                                 __half* __restrict__ o,
                                 const float* __restrict__ rw,
                                 const float* __restrict__ rb)
{
    int lane = threadIdx.x & 31, warp = threadIdx.x >> 5;
    int row = blockIdx.x * 8 + warp;
    const float* xr = x + (size_t)row * DD;
    float4 v[4];
    float s = 0.f, q = 0.f;
    float lg0=0.f, lg1=0.f, lg2=0.f, lg3=0.f;
    #pragma unroll
    for (int i = 0; i < 4; i++) {
        int c0 = (i*32 + lane)*4;
        v[i] = *(const float4*)(xr + c0);
        s += v[i].x + v[i].y + v[i].z + v[i].w;
        q += v[i].x*v[i].x + v[i].y*v[i].y + v[i].z*v[i].z + v[i].w*v[i].w;
        if (ROUTER) {
            #pragma unroll
            for (int j = 0; j < 4; j++) {
                float xv = (&v[i].x)[j];
                float4 r4 = *(const float4*)(rw + (c0 + j)*4);
                lg0 += xv*r4.x; lg1 += xv*r4.y; lg2 += xv*r4.z; lg3 += xv*r4.w;
            }
        }
    }
    #pragma unroll
    for (int off = 16; off > 0; off >>= 1) {
        s += __shfl_xor_sync(0xffffffffu, s, off);
        q += __shfl_xor_sync(0xffffffffu, q, off);
        if (ROUTER) {
            lg0 += __shfl_xor_sync(0xffffffffu, lg0, off);
            lg1 += __shfl_xor_sync(0xffffffffu, lg1, off);
            lg2 += __shfl_xor_sync(0xffffffffu, lg2, off);
            lg3 += __shfl_xor_sync(0xffffffffu, lg3, off);
        }
    }
    if (ROUTER && lane == 0) {
        float l[4] = {lg0 + rb[0], lg1 + rb[1], lg2 + rb[2], lg3 + rb[3]};
        float mx = fmaxf(fmaxf(l[0], l[1]), fmaxf(l[2], l[3]));
        float p[4]; float Z = 0.f;
        #pragma unroll
        for (int e = 0; e < 4; e++) { p[e] = expf(l[e] - mx); Z += p[e]; }
        float inv = 1.f/Z;
        *(float4*)(g_probs + row*4) = make_float4(p[0]*inv, p[1]*inv, p[2]*inv, p[3]*inv);
    }
    float mu = s * (1.f/DD);
    float var = q * (1.f/DD) - mu*mu;
    float rstd = rsqrtf(var + 1e-5f);
    __half* orow = o + (size_t)row * DD;
    #pragma unroll
    for (int i = 0; i < 4; i++) {
        int idx = (i*32 + lane)*4;
        float4 gv = *(const float4*)(g + idx);
        float4 bv = *(const float4*)(b + idx);
        float o0 = (v[i].x - mu)*rstd*gv.x + bv.x;
        float o1 = (v[i].y - mu)*rstd*gv.y + bv.y;
        float o2 = (v[i].z - mu)*rstd*gv.z + bv.z;
        float o3 = (v[i].w - mu)*rstd*gv.w + bv.w;
        *(uint2*)(orow + idx) = make_uint2(packh2(o0, o1), packh2(o2, o3));
    }
}

// ---------------- parallel per-(b,e) sort (prob desc, index asc) ----------------
__global__ void sort_kernel()
{
    __shared__ unsigned long long keys[NN];
    int b = blockIdx.x >> 2, e = blockIdx.x & 3;
    int t = threadIdx.x;                      // 1024
    for (int i = t; i < NN; i += 1024) {
        unsigned pb = __float_as_uint(g_probs[(b*NN+i)*4+e]);
        keys[i] = ((unsigned long long)(~pb) << 32) | (unsigned)i;
    }
    __syncthreads();
    for (int k = 2; k <= NN; k <<= 1) {
        for (int j = k >> 1; j > 0; j >>= 1) {
            #pragma unroll
            for (int w = 0; w < 2; w++) {
                int idx = t + w*1024;
                int l = idx ^ j;
                if (l > idx) {
                    bool asc = ((idx & k) == 0);
                    unsigned long long a = keys[idx], c2 = keys[l];
                    if ((a > c2) == asc) { keys[idx] = c2; keys[l] = a; }
                }
            }
            __syncthreads();
        }
    }
    for (int i = t; i < NN; i += 1024)
        g_sorted[(b*4+e)*NN + i] = (unsigned)(keys[i] & 0xFFFFFFFFull);
}

// ---------------- serial claim + deterministic permutation ----------------
__global__ void claim_kernel(float* __restrict__ out, int out_size)
{
    __shared__ int asg[NN];
    __shared__ int wsum[32];
    const int caps[4]  = {1024, 512, 256, 256};
    const int base4[4] = {0, 1024, 1536, 1792};
    int b = blockIdx.x, t = threadIdx.x;      // 1024
    int lane = t & 31, wid = t >> 5;
    asg[2*t] = -1; asg[2*t+1] = -1;
    __syncthreads();

    for (int e = 3; e >= 0; e--) {
        int id0 = (int)g_sorted[(b*4+e)*NN + 2*t];
        int id1 = (int)g_sorted[(b*4+e)*NN + 2*t+1];
        int v0 = (asg[id0] < 0) ? 1 : 0;
        int v1 = (asg[id1] < 0) ? 1 : 0;
        int s = v0 + v1, sc = s;
        #pragma unroll
        for (int o = 1; o < 32; o <<= 1) {
            int u = __shfl_up_sync(0xffffffff, sc, o);
            if (lane >= o) sc += u;
        }
        if (lane == 31) wsum[wid] = sc;
        __syncthreads();
        if (wid == 0) {
            int w = wsum[lane];
            #pragma unroll
            for (int o = 1; o < 32; o <<= 1) {
                int u = __shfl_up_sync(0xffffffff, w, o);
                if (lane >= o) w += u;
            }
            wsum[lane] = w;
        }
        __syncthreads();
        int bs = (wid > 0 ? wsum[wid-1] : 0) + (sc - s);
        if (v0 && (bs + v0) <= caps[e]) asg[id0] = e;
        if (v1 && (bs + v0 + v1) <= caps[e]) asg[id1] = e;
        __syncthreads();
    }

    for (int e = 0; e < 4; e++) {
        int v0 = (asg[2*t] == e) ? 1 : 0;
        int v1 = (asg[2*t+1] == e) ? 1 : 0;
        int s = v0 + v1, sc = s;
        #pragma unroll
        for (int o = 1; o < 32; o <<= 1) {
            int u = __shfl_up_sync(0xffffffff, sc, o);
            if (lane >= o) sc += u;
        }
        if (lane == 31) wsum[wid] = sc;
        __syncthreads();
        if (wid == 0) {
            int w = wsum[lane];
            #pragma unroll
            for (int o = 1; o < 32; o <<= 1) {
                int u = __shfl_up_sync(0xffffffff, w, o);
                if (lane >= o) w += u;
            }
            wsum[lane] = w;
        }
        __syncthreads();
        int bs = (wid > 0 ? wsum[wid-1] : 0) + (sc - s);
        if (v0) {
            int pos = base4[e] + bs;
            g_perm[b*NN + pos] = b*NN + 2*t;
            g_rps[b*NN + pos] = g_probs[(b*NN + 2*t)*4 + e];
        }
        if (v1) {
            int pos = base4[e] + bs + v0;
            g_perm[b*NN + pos] = b*NN + 2*t + 1;
            g_rps[b*NN + pos] = g_probs[(b*NN + 2*t + 1)*4 + e];
        }
        __syncthreads();
    }

    #pragma unroll
    for (int w = 0; w < 2; w++) {
        int i = 2*t + w;
        int a = asg[i]; if (a < 0) a = 0;
        int gi = b*NN + i;
        if (out_size >= TOK*DD + TOK)   out[TOK*DD + gi] = (float)a;
        if (out_size >= TOK*DD + 2*TOK) out[TOK*DD + TOK + gi] = g_probs[gi*4 + a];
    }
}

// ---------------- fp16 GEMM, cp.async 2-stage, 128x128 tile, fused epilogues ----------------
__device__ __forceinline__ float gelu_t(float v) {
    float c = v*v*v;
    float t = tanhf(0.7978845608028654f*(v + 0.044715f*c));
    return 0.5f*v*(1.f+t);
}

#define ASTAGE 10240   /* 128*40*2 bytes */
#define BSTAGE 8704    /* 32*136*2 bytes */

template<int EPI>
__global__ void tgemm_kernel(const __half* __restrict__ A, const __half* __restrict__ B,
                             void* __restrict__ Cv, int N, int K,
                             const float* __restrict__ bias,
                             const float* __restrict__ add,
                             const float* __restrict__ alpha)
{
    int bx = blockIdx.x, by = blockIdx.y;
    int d = d_of_tile(by & 15);
    int col0 = bx * 128;
    int tid  = threadIdx.x;         // 256
    int lane = tid & 31;
    int warp = tid >> 5;

    if (EPI == 0) { if ((col0 & 511) >= d) return; }
    if (EPI == 2) { if (col0 >= 4*d) return; }
    if (EPI == 1 || EPI == 3) {
        if (col0 >= d) {
            int rr = tid >> 1;
            int cc = (tid & 1) * 64;
            int rg = by*128 + rr;
            int orig = g_perm[rg];
            const float* src = (EPI == 1) ? (add + (size_t)orig*N) : (add + (size_t)rg*N);
            float* dst = (EPI == 1) ? ((float*)Cv + (size_t)rg*N) : ((float*)Cv + (size_t)orig*N);
            #pragma unroll
            for (int j = 0; j < 64; j += 4)
                *(float4*)(dst + col0 + cc + j) = *(const float4*)(src + col0 + cc + j);
            return;
        }
    }
    int Keff = (EPI == 3) ? 4*d : d;

    __shared__ __align__(16) __half As[2][128][40];
    __shared__ __align__(16) __half Bs[2][32][136];

    int wm = warp >> 2, wn = warp & 3;
    float c[4][4][4];
    #pragma unroll
    for (int i=0;i<4;i++)
        #pragma unroll
        for (int j=0;j<4;j++)
            #pragma unroll
            for (int r=0;r<4;r++) c[i][j][r]=0.f;

    int ar  = tid >> 1;
    int ach = (tid & 1) * 16;
    int rowA0 = by*128 + ar;
    int rowA = (EPI == 0) ? g_perm[rowA0] : rowA0;
    const __half* Ag = A + (size_t)rowA*K + ach;
    int bk  = tid >> 3;
    int bn0 = (tid & 7) * 16;
    const __half* Bg = B + (size_t)bk*N + col0 + bn0;

    uint32_t asb = (uint32_t)__cvta_generic_to_shared(&As[0][0][0]);
    uint32_t bsb = (uint32_t)__cvta_generic_to_shared(&Bs[0][0][0]);
    uint32_t aSlot = asb + ar*80 + ach*2;
    uint32_t bSlot = bsb + bk*272 + bn0*2;

    // prologue: stage 0
    cp_async16(aSlot, Ag);
    cp_async16(aSlot + 16, Ag + 8);
    cp_async16(bSlot, Bg);
    cp_async16(bSlot + 16, Bg + 8);
    cp_commit();

    int it = 0;
    for (int k0 = 0; k0 < Keff; k0 += 32, it++) {
        int cur = it & 1;
        cp_wait0();
        __syncthreads();
        if (k0 + 32 < Keff) {
            int nxt = cur ^ 1;
            const __half* Agn = Ag + k0 + 32;
            const __half* Bgn = Bg + (size_t)(k0 + 32)*N;
            cp_async16(aSlot + nxt*ASTAGE, Agn);
            cp_async16(aSlot + nxt*ASTAGE + 16, Agn + 8);
            cp_async16(bSlot + nxt*BSTAGE, Bgn);
            cp_async16(bSlot + nxt*BSTAGE + 16, Bgn + 8);
            cp_commit();
        }
        uint32_t ab = asb + cur*ASTAGE;
        uint32_t bb = bsb + cur*BSTAGE;
        #pragma unroll
        for (int kk = 0; kk < 32; kk += 16) {
            uint32_t af[4][4];
            #pragma unroll
            for (int am = 0; am < 4; am++) {
                int m = lane >> 3;
                int row = wm*64 + am*16 + (lane & 7) + (m & 1)*8;
                int col = kk + (m >> 1)*8;
                ldsm_x4(af[am][0], af[am][1], af[am][2], af[am][3], ab + row*80 + col*2);
            }
            #pragma unroll
            for (int an = 0; an < 4; an++) {
                int brow = kk + (lane & 15);
                int bcol = wn*32 + an*8;
                uint32_t b0, b1;
                ldsm_x2t(b0, b1, bb + brow*272 + bcol*2);
                #pragma unroll
                for (int am = 0; am < 4; am++)
                    mma_f16(c[am][an], af[am], b0, b1);
            }
        }
        __syncthreads();
    }

    float aval = (EPI == 3) ? alpha[0] : 0.f;
    #pragma unroll
    for (int am = 0; am < 4; am++) {
        int r0 = by*128 + wm*64 + am*16 + (lane>>2);
        int r1 = r0 + 8;
        float gate0 = (EPI == 3) ? (aval * g_rps[r0] + 1.f) : 0.f;
        float gate1 = (EPI == 3) ? (aval * g_rps[r1] + 1.f) : 0.f;
        int org0 = (EPI == 1 || EPI == 3) ? g_perm[r0] : 0;
        int org1 = (EPI == 1 || EPI == 3) ? g_perm[r1] : 0;
        #pragma unroll
        for (int an = 0; an < 4; an++) {
            int col = col0 + wn*32 + an*8 + (lane&3)*2;
            #pragma unroll
            for (int h2 = 0; h2 < 2; h2++) {
                int r = h2 ? r1 : r0;
                int org = h2 ? org1 : org0;
                float gate = h2 ? gate1 : gate0;
                float v0 = c[am][an][2*h2], v1 = c[am][an][2*h2+1];
                if (EPI == 0) {
                    float o0 = ((col & 511) < d)     ? v0 : 0.f;
                    float o1 = (((col+1) & 511) < d) ? v1 : 0.f;
                    *(uint32_t*)((__half*)Cv + (size_t)r*N + col) = packh2(o0, o1);
                } else if (EPI == 1) {
                    size_t xi = (size_t)org*N + col;
                    float o0 = add[xi]   + ((col   < d) ? (v0 + bias[col])   : 0.f);
                    float o1 = add[xi+1] + ((col+1 < d) ? (v1 + bias[col+1]) : 0.f);
                    *(float2*)((float*)Cv + (size_t)r*N + col) = make_float2(o0, o1);
                } else if (EPI == 2) {
                    float o0 = gelu_t(v0 + bias[col]);
                    float o1 = gelu_t(v1 + bias[col+1]);
                    *(uint32_t*)((__half*)Cv + (size_t)r*N + col) = packh2(o0, o1);
                } else {
                    size_t zi = (size_t)r*N + col;
                    float z0 = (col   < d) ? (v0 + bias[col])   : 0.f;
                    float z1 = (col+1 < d) ? (v1 + bias[col+1]) : 0.f;
                    float o0 = add[zi]   + gate * z0;
                    float o1 = add[zi+1] + gate * z1;
                    *(float2*)((float*)Cv + (size_t)org*N + col) = make_float2(o0, o1);
                }
            }
        }
    }
}

// ---------------- fp16 flash attention, intra-block split-K (2 groups) ----------------
// smem halves layout: Qs[64][72] | Ks0 | Ks1 | Vs0 | Vs1 (each [64][72])
#define QS_OFF 0
#define KS_OFF(g) (4608 + (g)*4608)
#define VS_OFF(g) (13824 + (g)*4608)

__global__ void attn_kernel()   // 256 threads = 2 warp-groups of 4 warps
{
    __shared__ __align__(16) __half sm[23040];

    int b = blockIdx.y;
    int qi = blockIdx.x;            // 0..79
    int h, qt;
    if (qi < 32)      { h = 0; qt = qi; }
    else if (qi < 48) { h = 1; qt = 16 + (qi - 32); }
    else if (qi < 56) { h = 2; qt = 24 + (qi - 48); }
    else if (qi < 64) { h = 3; qt = 24 + (qi - 56); }
    else              { h = 4 + ((qi - 64) >> 2); qt = 28 + ((qi - 64) & 3); }
    int kt0 = (h == 0) ? 0 : (h == 1) ? 16 : (h < 4) ? 24 : 28;
    int nz = kt0 * 64;

    int tid = threadIdx.x;
    int lane = tid & 31;
    int warp = tid >> 5;
    int grp = warp >> 2;            // 0/1
    int w4 = warp & 3;
    int ltid = tid & 127;

    int half = (32 - kt0) >> 1;
    int ktbeg = kt0 + grp*half;

    __half* Qs = sm + QS_OFF;
    __half* Ks = sm + KS_OFF(grp);
    __half* Vs = sm + VS_OFF(grp);
    uint32_t vsb = (uint32_t)__cvta_generic_to_shared(Vs);

    // load Q tile (all 256 threads)
    const __half* qb = g_qkv + (size_t)(b*NN + qt*64)*1536 + h*64;
    for (int i = tid; i < 512; i += 256) {
        int n = i >> 3, c8 = (i & 7) * 8;
        *(uint4*)(&Qs[n*72 + c8]) = *(const uint4*)(qb + (size_t)n*1536 + c8);
    }
    __syncthreads();

    uint32_t qf[4][4];
    {
        int r = w4*16 + (lane >> 2);
        #pragma unroll
        for (int ka = 0; ka < 4; ka++) {
            int cc = ka*16 + (lane & 3)*2;
            qf[ka][0] = *(const uint32_t*)(&Qs[r*72 + cc]);
            qf[ka][1] = *(const uint32_t*)(&Qs[(r+8)*72 + cc]);
            qf[ka][2] = *(const uint32_t*)(&Qs[r*72 + cc + 8]);
            qf[ka][3] = *(const uint32_t*)(&Qs[(r+8)*72 + cc + 8]);
        }
    }

    float o[8][4];
    #pragma unroll
    for (int i=0;i<8;i++)
        #pragma unroll
        for (int j=0;j<4;j++) o[i][j]=0.f;
    float m0, m1, l0, l1;
    if (grp == 0 && nz > 0) { m0 = 0.f; m1 = 0.f; l0 = (float)nz; l1 = (float)nz; }
    else                    { m0 = -1e30f; m1 = -1e30f; l0 = 0.f; l1 = 0.f; }

    for (int ii = 0; ii < half; ii++) {
        int kt = ktbeg + ii;
        __syncthreads();
        const __half* kb = g_qkv + (size_t)(b*NN + kt*64)*1536 + 512 + h*64;
        for (int i = ltid; i < 512; i += 128) {
            int n = i >> 3, c8 = (i & 7) * 8;
            *(uint4*)(&Ks[n*72 + c8]) = *(const uint4*)(kb + (size_t)n*1536 + c8);
            *(uint4*)(&Vs[n*72 + c8]) = *(const uint4*)(kb + 512 + (size_t)n*1536 + c8);
        }
        __syncthreads();

        float s[8][4];
        #pragma unroll
        for (int i=0;i<8;i++)
            #pragma unroll
            for (int j=0;j<4;j++) s[i][j]=0.f;
        #pragma unroll
        for (int ka = 0; ka < 4; ka++) {
            #pragma unroll
            for (int na = 0; na < 8; na++) {
                int n = na*8 + (lane >> 2);
                int k = ka*16 + (lane & 3)*2;
                uint32_t b0 = *(const uint32_t*)(&Ks[n*72 + k]);
                uint32_t b1 = *(const uint32_t*)(&Ks[n*72 + k + 8]);
                mma_f16(s[na], qf[ka], b0, b1);
            }
        }

        float mx0 = -1e30f, mx1 = -1e30f;
        #pragma unroll
        for (int na = 0; na < 8; na++) {
            s[na][0]*=0.125f; s[na][1]*=0.125f; s[na][2]*=0.125f; s[na][3]*=0.125f;
            mx0 = fmaxf(mx0, fmaxf(s[na][0], s[na][1]));
            mx1 = fmaxf(mx1, fmaxf(s[na][2], s[na][3]));
        }
        mx0 = fmaxf(mx0, __shfl_xor_sync(0xffffffffu, mx0, 1));
        mx0 = fmaxf(mx0, __shfl_xor_sync(0xffffffffu, mx0, 2));
        mx1 = fmaxf(mx1, __shfl_xor_sync(0xffffffffu, mx1, 1));
        mx1 = fmaxf(mx1, __shfl_xor_sync(0xffffffffu, mx1, 2));
        float mn0 = fmaxf(m0, mx0), mn1 = fmaxf(m1, mx1);
        float sc0 = __expf(m0 - mn0), sc1 = __expf(m1 - mn1);
        m0 = mn0; m1 = mn1;

        float sum0 = 0.f, sum1 = 0.f;
        #pragma unroll
        for (int na = 0; na < 8; na++) {
            s[na][0] = __expf(s[na][0] - m0);
            s[na][1] = __expf(s[na][1] - m0);
            s[na][2] = __expf(s[na][2] - m1);
            s[na][3] = __expf(s[na][3] - m1);
            sum0 += s[na][0] + s[na][1];
            sum1 += s[na][2] + s[na][3];
        }
        sum0 += __shfl_xor_sync(0xffffffffu, sum0, 1);
        sum0 += __shfl_xor_sync(0xffffffffu, sum0, 2);
        sum1 += __shfl_xor_sync(0xffffffffu, sum1, 1);
        sum1 += __shfl_xor_sync(0xffffffffu, sum1, 2);
        l0 = l0*sc0 + sum0;
        l1 = l1*sc1 + sum1;

        #pragma unroll
        for (int da = 0; da < 8; da++) {
            o[da][0]*=sc0; o[da][1]*=sc0; o[da][2]*=sc1; o[da][3]*=sc1;
        }

        #pragma unroll
        for (int ka = 0; ka < 4; ka++) {
            uint32_t pa[4];
            pa[0] = packh2(s[2*ka][0],   s[2*ka][1]);
            pa[1] = packh2(s[2*ka][2],   s[2*ka][3]);
            pa[2] = packh2(s[2*ka+1][0], s[2*ka+1][1]);
            pa[3] = packh2(s[2*ka+1][2], s[2*ka+1][3]);
            uint32_t rowaddr = vsb + (ka*16 + (lane & 15))*144;
            #pragma unroll
            for (int da = 0; da < 8; da++) {
                uint32_t b0, b1;
                ldsm_x2t(b0, b1, rowaddr + da*16);
                mma_f16(o[da], pa, b0, b1);
            }
        }
    }

    // merge group 1 into group 0 via smem staging (aliases Qs/Ks0 — dead now)
    __syncthreads();
    float* so = (float*)sm;                 // [64][66] floats
    float* sml = so + 64*66;                // m[64], l[64]
    int r0 = w4*16 + (lane >> 2);
    int r1 = r0 + 8;
    if (grp == 1) {
        #pragma unroll
        for (int da = 0; da < 8; da++) {
            int col = da*8 + (lane&3)*2;
            *(float2*)(&so[r0*66 + col]) = make_float2(o[da][0], o[da][1]);
            *(float2*)(&so[r1*66 + col]) = make_float2(o[da][2], o[da][3]);
        }
        if ((lane & 3) == 0) {
            sml[r0] = m0; sml[64 + r0] = l0;
            sml[r1] = m1; sml[64 + r1] = l1;
        }
    }
    __syncthreads();
    if (grp == 0) {
        float m1s0 = sml[r0], l1s0 = sml[64 + r0];
        float m1s1 = sml[r1], l1s1 = sml[64 + r1];
        float M0 = fmaxf(m0, m1s0), M1 = fmaxf(m1, m1s1);
        float a0 = __expf(m0 - M0), b0s = __expf(m1s0 - M0);
        float a1 = __expf(m1 - M1), b1s = __expf(m1s1 - M1);
        float L0 = l0*a0 + l1s0*b0s;
        float L1 = l1*a1 + l1s1*b1s;
        float inv0 = 1.f / L0, inv1 = 1.f / L1;
        int tok0 = b*NN + qt*64 + r0;
        int tok1 = tok0 + 8;
        #pragma unroll
        for (int da = 0; da < 8; da++) {
            int col = da*8 + (lane&3)*2;
            float2 p0 = *(float2*)(&so[r0*66 + col]);
            float2 p1 = *(float2*)(&so[r1*66 + col]);
            float f00 = (o[da][0]*a0 + p0.x*b0s) * inv0;
            float f01 = (o[da][1]*a0 + p0.y*b0s) * inv0;
            float f10 = (o[da][2]*a1 + p1.x*b1s) * inv1;
            float f11 = (o[da][3]*a1 + p1.y*b1s) * inv1;
            int gcol = h*64 + col;
            *(uint32_t*)(g_o + (size_t)tok0*DD + gcol) = packh2(f00, f01);
            *(uint32_t*)(g_o + (size_t)tok1*DD + gcol) = packh2(f10, f11);
        }
    }
}

// ---------------- launcher ----------------
extern "C" void kernel_launch(void* const* d_in, const int* in_sizes, int n_in,
                              void* d_out, int out_size)
{
    const float* x     = (const float*)d_in[0];
    const float* r_w   = (const float*)d_in[1];
    const float* r_b   = (const float*)d_in[2];
    const float* g1    = (const float*)d_in[3];
    const float* b1    = (const float*)d_in[4];
    const float* g2    = (const float*)d_in[5];
    const float* b2    = (const float*)d_in[6];
    const float* w_qkv = (const float*)d_in[7];
    const float* w_o   = (const float*)d_in[8];
    const float* b_o   = (const float*)d_in[9];
    const float* w1    = (const float*)d_in[10];
    const float* b1f   = (const float*)d_in[11];
    const float* w2    = (const float*)d_in[12];
    const float* b2f   = (const float*)d_in[13];
    const float* alpha = (const float*)d_in[14];
    float* out = (float*)d_out;

    __half *p_h, *p_qkv, *p_o, *p_hid, *p_wh;
    float *p_z;
    cudaGetSymbolAddress((void**)&p_h,   g_h);
    cudaGetSymbolAddress((void**)&p_qkv, g_qkv);
    cudaGetSymbolAddress((void**)&p_o,   g_o);
    cudaGetSymbolAddress((void**)&p_z,   g_z);
    cudaGetSymbolAddress((void**)&p_hid, g_hid);
    cudaGetSymbolAddress((void**)&p_wh,  g_wh);

    // weights -> fp16 (independent of routing)
    wconv_kernel<<<(W_TOTAL/4 + 255)/256, 256>>>(w_qkv, w_o, w1, w2);

    // fused LN1 + router (original token order)
    ln_router_kernel<true><<<TOK/8, 256>>>(x, g1, b1, p_h, r_w, r_b);
    sort_kernel<<<BB*EE, 1024>>>();
    claim_kernel<<<BB, 1024>>>(out, out_size);

    // attention path
    tgemm_kernel<0><<<dim3(1536/128, TOK/128), 256>>>(p_h, p_wh + W_QKV_OFF, p_qkv, 1536, 512,
                                                      nullptr, nullptr, nullptr);
    attn_kernel<<<dim3(80, BB), 256>>>();
    tgemm_kernel<1><<<dim3(512/128, TOK/128), 256>>>(p_o, p_wh + W_O_OFF, p_z, 512, 512,
                                                     b_o, x, nullptr);

    // feed-forward path
    ln_router_kernel<false><<<TOK/8, 256>>>(p_z, g2, b2, p_h, nullptr, nullptr);
    tgemm_kernel<2><<<dim3(2048/128, TOK/128), 256>>>(p_h, p_wh + W1_OFF, p_hid, 2048, 512,
                                                      b1f, nullptr, nullptr);
    tgemm_kernel<3><<<dim3(512/128, TOK/128), 256>>>(p_hid, p_wh + W2_OFF, out, 512, 2048,
                                                     b2f, p_z, alpha);
}